// round 2
// baseline (speedup 1.0000x reference)
#include <cuda_runtime.h>
#include <math.h>
#include <cstddef>

// ---------------- problem constants ----------------
#define B_    4096
#define DIN   512
#define DH    1024
#define DOUT  256
#define DFF   4096
#define STEPS 30
#define LN_EPSF 1e-5f
// GAMMA = 0.5 * sqrt(64/512)
#define GAMMA_F 0.17677669529663687f

// ---------------- device scratch (no allocations allowed) ----------------
__device__ float g_W1n[(size_t)DFF * DH];
__device__ float g_W2n[(size_t)DH * DFF];
__device__ float g_xemb[(size_t)B_ * DH];
__device__ float g_hA[(size_t)B_ * DH];
__device__ float g_hB[(size_t)B_ * DH];
__device__ float g_hn[(size_t)B_ * DH];
__device__ float g_hid[(size_t)B_ * DFF];
__device__ float g_u[4096];
__device__ float g_v[4096];
__device__ float g_t[4096];
__device__ float g_sig[2];

// ---------------- small kernels: spectral norm ----------------
__global__ void init_vec_kernel(float* v, int n, float val) {
    int i = blockIdx.x * blockDim.x + threadIdx.x;
    if (i < n) v[i] = val;
}

// y[row] = dot(W[row,:], v)   W is [R,C] row-major; grid = R blocks, 256 thr
__global__ void matvec_rows(const float* __restrict__ W, const float* __restrict__ v,
                            float* __restrict__ y, int C) {
    int row = blockIdx.x;
    const float* Wr = W + (size_t)row * C;
    float acc = 0.f;
    for (int j = threadIdx.x; j < C; j += 256) acc += Wr[j] * v[j];
    __shared__ float sm[8];
    #pragma unroll
    for (int o = 16; o > 0; o >>= 1) acc += __shfl_down_sync(0xffffffffu, acc, o);
    if ((threadIdx.x & 31) == 0) sm[threadIdx.x >> 5] = acc;
    __syncthreads();
    if (threadIdx.x < 8) {
        float a = sm[threadIdx.x];
        #pragma unroll
        for (int o = 4; o > 0; o >>= 1) a += __shfl_down_sync(0xffu, a, o);
        if (threadIdx.x == 0) y[row] = a;
    }
}

// z[col] = dot(W[:,col], u)   grid = C/32 blocks, 256 thr (32 cols x 8 row-groups)
__global__ void matvec_cols(const float* __restrict__ W, const float* __restrict__ u,
                            float* __restrict__ z, int R, int C) {
    int lane = threadIdx.x & 31;
    int rp   = threadIdx.x >> 5;   // 0..7
    int col  = blockIdx.x * 32 + lane;
    float acc = 0.f;
    for (int i = rp; i < R; i += 8) acc += W[(size_t)i * C + col] * u[i];
    __shared__ float sm[8][33];
    sm[rp][lane] = acc;
    __syncthreads();
    if (rp == 0) {
        float a = 0.f;
        #pragma unroll
        for (int r = 0; r < 8; r++) a += sm[r][lane];
        z[col] = a;
    }
}

// in-place: v = v / (||v|| + 1e-12); single block of 1024 threads
__global__ void normalize_vec(float* v, int n) {
    __shared__ float sm[32];
    __shared__ float s_inv;
    float acc = 0.f;
    for (int i = threadIdx.x; i < n; i += 1024) { float x = v[i]; acc += x * x; }
    #pragma unroll
    for (int o = 16; o > 0; o >>= 1) acc += __shfl_down_sync(0xffffffffu, acc, o);
    if ((threadIdx.x & 31) == 0) sm[threadIdx.x >> 5] = acc;
    __syncthreads();
    if (threadIdx.x < 32) {
        float a = sm[threadIdx.x];
        #pragma unroll
        for (int o = 16; o > 0; o >>= 1) a += __shfl_down_sync(0xffffffffu, a, o);
        if (threadIdx.x == 0) s_inv = 1.0f / (sqrtf(a) + 1e-12f);
    }
    __syncthreads();
    float inv = s_inv;
    for (int i = threadIdx.x; i < n; i += 1024) v[i] *= inv;
}

// out[0] = dot(a,b); single block of 1024 threads
__global__ void dot_kernel(const float* __restrict__ a, const float* __restrict__ b,
                           float* __restrict__ out, int n) {
    __shared__ float sm[32];
    float acc = 0.f;
    for (int i = threadIdx.x; i < n; i += 1024) acc += a[i] * b[i];
    #pragma unroll
    for (int o = 16; o > 0; o >>= 1) acc += __shfl_down_sync(0xffffffffu, acc, o);
    if ((threadIdx.x & 31) == 0) sm[threadIdx.x >> 5] = acc;
    __syncthreads();
    if (threadIdx.x < 32) {
        float a2 = sm[threadIdx.x];
        #pragma unroll
        for (int o = 16; o > 0; o >>= 1) a2 += __shfl_down_sync(0xffffffffu, a2, o);
        if (threadIdx.x == 0) out[0] = a2;
    }
}

__global__ void scale_by_sigma(const float* __restrict__ W, float* __restrict__ Wn,
                               const float* __restrict__ sig, size_t n) {
    float inv = 1.0f / sig[0];
    size_t stride = (size_t)gridDim.x * blockDim.x;
    for (size_t i = (size_t)blockIdx.x * blockDim.x + threadIdx.x; i < n; i += stride)
        Wn[i] = W[i] * inv;
}

// ---------------- layernorm: one block (256 thr) per row of DH=1024 ----------------
__global__ void layernorm_kernel(const float* __restrict__ h,
                                 const float* __restrict__ g, const float* __restrict__ b,
                                 float* __restrict__ out) {
    int row = blockIdx.x;
    const float* hr = h + (size_t)row * DH;
    float s = 0.f, ss = 0.f;
    float xl[4];
    #pragma unroll
    for (int t = 0; t < 4; t++) {
        float x = hr[threadIdx.x + t * 256];
        xl[t] = x; s += x; ss += x * x;
    }
    __shared__ float sm1[8], sm2[8];
    #pragma unroll
    for (int o = 16; o > 0; o >>= 1) {
        s  += __shfl_down_sync(0xffffffffu, s, o);
        ss += __shfl_down_sync(0xffffffffu, ss, o);
    }
    if ((threadIdx.x & 31) == 0) { sm1[threadIdx.x >> 5] = s; sm2[threadIdx.x >> 5] = ss; }
    __syncthreads();
    __shared__ float s_mu, s_inv;
    if (threadIdx.x < 8) {
        float a = sm1[threadIdx.x], c = sm2[threadIdx.x];
        #pragma unroll
        for (int o = 4; o > 0; o >>= 1) {
            a += __shfl_down_sync(0xffu, a, o);
            c += __shfl_down_sync(0xffu, c, o);
        }
        if (threadIdx.x == 0) {
            float mu  = a * (1.0f / DH);
            float var = c * (1.0f / DH) - mu * mu;
            s_mu = mu; s_inv = rsqrtf(var + LN_EPSF);
        }
    }
    __syncthreads();
    float mu = s_mu, inv = s_inv;
    #pragma unroll
    for (int t = 0; t < 4; t++) {
        int j = threadIdx.x + t * 256;
        out[(size_t)row * DH + j] = (xl[t] - mu) * inv * g[j] + b[j];
    }
}

// ---------------- tiled fp32 GEMM: C[M,N] = A[M,K] * W[N,K]^T + epi ----------------
#define BM 128
#define BN 128
#define BK 8
#define TM 8
#define TN 8

#define EPI_BIAS 0
#define EPI_TANH 1
#define EPI_STEP 2

template <int EPI>
__global__ __launch_bounds__(256, 2) void gemm_atb(
    const float* __restrict__ A, const float* __restrict__ W,
    const float* __restrict__ bias, float* __restrict__ C,
    int M, int N, int K,
    const float* __restrict__ hprev, const float* __restrict__ xemb, float gamma) {

    __shared__ __align__(16) float As[BK][BM];
    __shared__ __align__(16) float Ws[BK][BN];

    int tid = threadIdx.x;
    int bm = blockIdx.y * BM, bn = blockIdx.x * BN;
    const float* Ablk = A + (size_t)bm * K;
    const float* Wblk = W + (size_t)bn * K;

    int lrow = tid >> 1;          // 0..127
    int lcol = (tid & 1) * 4;     // 0 or 4
    int ty = tid >> 4, tx = tid & 15;

    float acc[TM][TN] = {};

    for (int k0 = 0; k0 < K; k0 += BK) {
        float4 a4 = *reinterpret_cast<const float4*>(Ablk + (size_t)lrow * K + k0 + lcol);
        float4 w4 = *reinterpret_cast<const float4*>(Wblk + (size_t)lrow * K + k0 + lcol);
        As[lcol + 0][lrow] = a4.x; As[lcol + 1][lrow] = a4.y;
        As[lcol + 2][lrow] = a4.z; As[lcol + 3][lrow] = a4.w;
        Ws[lcol + 0][lrow] = w4.x; Ws[lcol + 1][lrow] = w4.y;
        Ws[lcol + 2][lrow] = w4.z; Ws[lcol + 3][lrow] = w4.w;
        __syncthreads();
        #pragma unroll
        for (int k = 0; k < BK; k++) {
            float4 a0 = *reinterpret_cast<const float4*>(&As[k][ty * TM]);
            float4 a1 = *reinterpret_cast<const float4*>(&As[k][ty * TM + 4]);
            float4 w0 = *reinterpret_cast<const float4*>(&Ws[k][tx * TN]);
            float4 w1 = *reinterpret_cast<const float4*>(&Ws[k][tx * TN + 4]);
            float ra[TM] = {a0.x, a0.y, a0.z, a0.w, a1.x, a1.y, a1.z, a1.w};
            float rw[TN] = {w0.x, w0.y, w0.z, w0.w, w1.x, w1.y, w1.z, w1.w};
            #pragma unroll
            for (int i = 0; i < TM; i++)
                #pragma unroll
                for (int j = 0; j < TN; j++)
                    acc[i][j] += ra[i] * rw[j];
        }
        __syncthreads();
    }

    #pragma unroll
    for (int i = 0; i < TM; i++) {
        int m = bm + ty * TM + i;
        #pragma unroll
        for (int j = 0; j < TN; j++) {
            int n = bn + tx * TN + j;
            float c = acc[i][j] + bias[n];
            if (EPI == EPI_TANH) c = tanhf(c);
            if (EPI == EPI_STEP) {
                size_t idx = (size_t)m * N + n;
                c = (1.0f - gamma) * hprev[idx] + gamma * (c + xemb[idx]);
            }
            C[(size_t)m * N + n] = c;
        }
    }
}

// ---------------- host-side helpers ----------------
static void spectral_normalize(const float* W, float* Wn, int R, int C,
                               float* u, float* v, float* t, float* sig) {
    float v0 = 1.0f / sqrtf((float)C);
    init_vec_kernel<<<(C + 255) / 256, 256>>>(v, C, v0);
    for (int it = 0; it < 15; it++) {
        matvec_rows<<<R, 256>>>(W, v, u, C);
        normalize_vec<<<1, 1024>>>(u, R);
        matvec_cols<<<C / 32, 256>>>(W, u, v, R, C);
        normalize_vec<<<1, 1024>>>(v, C);
    }
    matvec_rows<<<R, 256>>>(W, v, t, C);
    dot_kernel<<<1, 1024>>>(u, t, sig, R);
    size_t n = (size_t)R * C;
    scale_by_sigma<<<2048, 256>>>(W, Wn, sig, n);
}

extern "C" void kernel_launch(void* const* d_in, const int* in_sizes, int n_in,
                              void* d_out, int out_size) {
    const float* x       = (const float*)d_in[0];
    const float* embed_w = (const float*)d_in[1];
    const float* embed_b = (const float*)d_in[2];
    const float* W1      = (const float*)d_in[3];
    const float* b1      = (const float*)d_in[4];
    const float* W2      = (const float*)d_in[5];
    const float* b2      = (const float*)d_in[6];
    const float* ln_g    = (const float*)d_in[7];
    const float* ln_b    = (const float*)d_in[8];
    const float* head_w  = (const float*)d_in[9];
    const float* head_b  = (const float*)d_in[10];
    float* out = (float*)d_out;

    float *p_W1n, *p_W2n, *p_xemb, *p_hA, *p_hB, *p_hn, *p_hid, *p_u, *p_v, *p_t, *p_sig;
    cudaGetSymbolAddress((void**)&p_W1n, g_W1n);
    cudaGetSymbolAddress((void**)&p_W2n, g_W2n);
    cudaGetSymbolAddress((void**)&p_xemb, g_xemb);
    cudaGetSymbolAddress((void**)&p_hA, g_hA);
    cudaGetSymbolAddress((void**)&p_hB, g_hB);
    cudaGetSymbolAddress((void**)&p_hn, g_hn);
    cudaGetSymbolAddress((void**)&p_hid, g_hid);
    cudaGetSymbolAddress((void**)&p_u, g_u);
    cudaGetSymbolAddress((void**)&p_v, g_v);
    cudaGetSymbolAddress((void**)&p_t, g_t);
    cudaGetSymbolAddress((void**)&p_sig, g_sig);

    // Spectral normalization of W1 [DFF,DH] and W2 [DH,DFF]
    spectral_normalize(W1, p_W1n, DFF, DH, p_u, p_v, p_t, p_sig);
    spectral_normalize(W2, p_W2n, DH, DFF, p_u, p_v, p_t, p_sig);

    // x_emb = x @ embed_w^T + embed_b
    gemm_atb<EPI_BIAS><<<dim3(DH / BN, B_ / BM), 256>>>(
        x, embed_w, embed_b, p_xemb, B_, DH, DIN, nullptr, nullptr, 0.f);

    // h0 = x_emb
    cudaMemcpyAsync(p_hA, p_xemb, (size_t)B_ * DH * sizeof(float),
                    cudaMemcpyDeviceToDevice);

    float* hc = p_hA;
    float* hx = p_hB;
    for (int s = 0; s < STEPS; s++) {
        layernorm_kernel<<<B_, 256>>>(hc, ln_g, ln_b, p_hn);
        gemm_atb<EPI_TANH><<<dim3(DFF / BN, B_ / BM), 256>>>(
            p_hn, p_W1n, b1, p_hid, B_, DFF, DH, nullptr, nullptr, 0.f);
        gemm_atb<EPI_STEP><<<dim3(DH / BN, B_ / BM), 256>>>(
            p_hid, p_W2n, b2, hx, B_, DH, DFF, hc, p_xemb, GAMMA_F);
        float* tmp = hc; hc = hx; hx = tmp;
    }

    // out = h @ head_w^T + head_b
    gemm_atb<EPI_BIAS><<<dim3(DOUT / BN, B_ / BM), 256>>>(
        hc, head_w, head_b, out, B_, DOUT, DH, nullptr, nullptr, 0.f);
}

// round 4
// speedup vs baseline: 2.5598x; 2.5598x over previous
#include <cuda_runtime.h>
#include <cuda_bf16.h>
#include <math.h>
#include <cstddef>
#include <cstdint>

// ---------------- problem constants ----------------
#define B_    4096
#define DIN   512
#define DH    1024
#define DOUT  256
#define DFF   4096
#define STEPS 30
#define LN_EPSF 1e-5f
#define GAMMA_F 0.17677669529663687f   // 0.5*sqrt(64/512)

// ---------------- device scratch (no allocations allowed) ----------------
__device__ float g_xemb[(size_t)B_ * DH];
__device__ float g_hA[(size_t)B_ * DH];
__device__ float g_hB[(size_t)B_ * DH];
__device__ __nv_bfloat16 g_W1hi[(size_t)DFF * DH];
__device__ __nv_bfloat16 g_W1lo[(size_t)DFF * DH];
__device__ __nv_bfloat16 g_W2hi[(size_t)DH * DFF];
__device__ __nv_bfloat16 g_W2lo[(size_t)DH * DFF];
__device__ __nv_bfloat16 g_hnhi[(size_t)B_ * DH];
__device__ __nv_bfloat16 g_hnlo[(size_t)B_ * DH];
__device__ __nv_bfloat16 g_hidhi[(size_t)B_ * DFF];
__device__ __nv_bfloat16 g_hidlo[(size_t)B_ * DFF];
__device__ float g_u[4096];
__device__ float g_v[4096];
__device__ float g_t[4096];
__device__ float g_sig[2];

// ---------------- low-level helpers (all plain sm_80+ features) ----------------
__device__ __forceinline__ uint32_t smem_u32(const void* p) {
    uint32_t a;
    asm("{ .reg .u64 t; cvta.to.shared.u64 t, %1; cvt.u32.u64 %0, t; }" : "=r"(a) : "l"(p));
    return a;
}
__device__ __forceinline__ void cp_async16(uint32_t dst, const void* src) {
    asm volatile("cp.async.cg.shared.global [%0], [%1], 16;" :: "r"(dst), "l"(src) : "memory");
}
__device__ __forceinline__ void cp_commit() {
    asm volatile("cp.async.commit_group;" ::: "memory");
}
template<int N> __device__ __forceinline__ void cp_wait() {
    asm volatile("cp.async.wait_group %0;" :: "n"(N) : "memory");
}
__device__ __forceinline__ void ldm_x4(uint32_t addr, uint32_t* r) {
    asm volatile("ldmatrix.sync.aligned.m8n8.x4.shared.b16 {%0,%1,%2,%3}, [%4];"
        : "=r"(r[0]), "=r"(r[1]), "=r"(r[2]), "=r"(r[3]) : "r"(addr));
}
__device__ __forceinline__ void mma16816(float* d, const uint32_t* a, const uint32_t* b) {
    asm volatile("mma.sync.aligned.m16n8k16.row.col.f32.bf16.bf16.f32 "
        "{%0,%1,%2,%3}, {%4,%5,%6,%7}, {%8,%9}, {%0,%1,%2,%3};"
        : "+f"(d[0]), "+f"(d[1]), "+f"(d[2]), "+f"(d[3])
        : "r"(a[0]), "r"(a[1]), "r"(a[2]), "r"(a[3]), "r"(b[0]), "r"(b[1]));
}

// ---------------- small kernels: spectral norm ----------------
__global__ void init_vec_kernel(float* v, int n, float val) {
    int i = blockIdx.x * blockDim.x + threadIdx.x;
    if (i < n) v[i] = val;
}

__global__ void matvec_rows(const float* __restrict__ W, const float* __restrict__ v,
                            float* __restrict__ y, int C) {
    int row = blockIdx.x;
    const float* Wr = W + (size_t)row * C;
    float acc = 0.f;
    for (int j = threadIdx.x; j < C; j += 256) acc += Wr[j] * v[j];
    __shared__ float sm[8];
    #pragma unroll
    for (int o = 16; o > 0; o >>= 1) acc += __shfl_down_sync(0xffffffffu, acc, o);
    if ((threadIdx.x & 31) == 0) sm[threadIdx.x >> 5] = acc;
    __syncthreads();
    if (threadIdx.x < 8) {
        float a = sm[threadIdx.x];
        #pragma unroll
        for (int o = 4; o > 0; o >>= 1) a += __shfl_down_sync(0xffu, a, o);
        if (threadIdx.x == 0) y[row] = a;
    }
}

// z[col] += partial dot(W[:,col], u); grid (C/32, 8); z must be zeroed first
__global__ void matvec_cols(const float* __restrict__ W, const float* __restrict__ u,
                            float* __restrict__ z, int R, int C) {
    int lane = threadIdx.x & 31;
    int rp   = threadIdx.x >> 5;
    int col  = blockIdx.x * 32 + lane;
    int rchunk = R >> 3;
    int r0 = blockIdx.y * rchunk;
    int r1 = r0 + rchunk;
    float acc = 0.f;
    for (int i = r0 + rp; i < r1; i += 8) acc += W[(size_t)i * C + col] * u[i];
    __shared__ float sm[8][33];
    sm[rp][lane] = acc;
    __syncthreads();
    if (rp == 0) {
        float a = 0.f;
        #pragma unroll
        for (int r = 0; r < 8; r++) a += sm[r][lane];
        atomicAdd(&z[col], a);
    }
}

__global__ void normalize_vec(float* v, int n) {
    __shared__ float sm[32];
    __shared__ float s_inv;
    float acc = 0.f;
    for (int i = threadIdx.x; i < n; i += 1024) { float x = v[i]; acc += x * x; }
    #pragma unroll
    for (int o = 16; o > 0; o >>= 1) acc += __shfl_down_sync(0xffffffffu, acc, o);
    if ((threadIdx.x & 31) == 0) sm[threadIdx.x >> 5] = acc;
    __syncthreads();
    if (threadIdx.x < 32) {
        float a = sm[threadIdx.x];
        #pragma unroll
        for (int o = 16; o > 0; o >>= 1) a += __shfl_down_sync(0xffffffffu, a, o);
        if (threadIdx.x == 0) s_inv = 1.0f / (sqrtf(a) + 1e-12f);
    }
    __syncthreads();
    float inv = s_inv;
    for (int i = threadIdx.x; i < n; i += 1024) v[i] *= inv;
}

__global__ void dot_kernel(const float* __restrict__ a, const float* __restrict__ b,
                           float* __restrict__ out, int n) {
    __shared__ float sm[32];
    float acc = 0.f;
    for (int i = threadIdx.x; i < n; i += 1024) acc += a[i] * b[i];
    #pragma unroll
    for (int o = 16; o > 0; o >>= 1) acc += __shfl_down_sync(0xffffffffu, acc, o);
    if ((threadIdx.x & 31) == 0) sm[threadIdx.x >> 5] = acc;
    __syncthreads();
    if (threadIdx.x < 32) {
        float a2 = sm[threadIdx.x];
        #pragma unroll
        for (int o = 16; o > 0; o >>= 1) a2 += __shfl_down_sync(0xffffffffu, a2, o);
        if (threadIdx.x == 0) out[0] = a2;
    }
}

// Wn = W / sigma, split into bf16 hi/lo pair
__global__ void scale_split(const float* __restrict__ W, const float* __restrict__ sig,
                            __nv_bfloat16* __restrict__ hi, __nv_bfloat16* __restrict__ lo,
                            size_t n) {
    float inv = 1.0f / sig[0];
    size_t stride = (size_t)gridDim.x * blockDim.x;
    for (size_t i = (size_t)blockIdx.x * blockDim.x + threadIdx.x; i < n; i += stride) {
        float w = W[i] * inv;
        __nv_bfloat16 h = __float2bfloat16(w);
        hi[i] = h;
        lo[i] = __float2bfloat16(w - __bfloat162float(h));
    }
}

// ---------------- layernorm: fp32 in, bf16 hi/lo out ----------------
__global__ void layernorm_split(const float* __restrict__ h,
                                const float* __restrict__ g, const float* __restrict__ b,
                                __nv_bfloat16* __restrict__ ohi, __nv_bfloat16* __restrict__ olo) {
    int row = blockIdx.x;
    const float* hr = h + (size_t)row * DH;
    float s = 0.f, ss = 0.f;
    float xl[4];
    #pragma unroll
    for (int t = 0; t < 4; t++) {
        float x = hr[threadIdx.x + t * 256];
        xl[t] = x; s += x; ss += x * x;
    }
    __shared__ float sm1[8], sm2[8];
    #pragma unroll
    for (int o = 16; o > 0; o >>= 1) {
        s  += __shfl_down_sync(0xffffffffu, s, o);
        ss += __shfl_down_sync(0xffffffffu, ss, o);
    }
    if ((threadIdx.x & 31) == 0) { sm1[threadIdx.x >> 5] = s; sm2[threadIdx.x >> 5] = ss; }
    __syncthreads();
    __shared__ float s_mu, s_inv;
    if (threadIdx.x < 8) {
        float a = sm1[threadIdx.x], c = sm2[threadIdx.x];
        #pragma unroll
        for (int o = 4; o > 0; o >>= 1) {
            a += __shfl_down_sync(0xffu, a, o);
            c += __shfl_down_sync(0xffu, c, o);
        }
        if (threadIdx.x == 0) {
            float mu  = a * (1.0f / DH);
            float var = c * (1.0f / DH) - mu * mu;
            s_mu = mu; s_inv = rsqrtf(var + LN_EPSF);
        }
    }
    __syncthreads();
    float mu = s_mu, inv = s_inv;
    #pragma unroll
    for (int t = 0; t < 4; t++) {
        int j = threadIdx.x + t * 256;
        float y = (xl[t] - mu) * inv * g[j] + b[j];
        __nv_bfloat16 hh = __float2bfloat16(y);
        size_t idx = (size_t)row * DH + j;
        ohi[idx] = hh;
        olo[idx] = __float2bfloat16(y - __bfloat162float(hh));
    }
}

// ---------------- HMMA bf16x3-split GEMM ----------------
// C[M,N] = (Ahi+Alo)[M,K] @ ((Whi+Wlo)[N,K])^T, 3 first-order terms.
// CTA tile 128x128, 8 warps (2x4), warp tile 64x32 = 4x4 m16n8k16 frags.
// BK=32, 4-stage cp.async pipeline, 80B-padded smem rows (conflict-free ldmatrix).
#define MSTAGES 4
#define ROWB    80
#define TILEB   (128 * ROWB)         // 10240 B per 128x32 bf16 tile
#define STAGEB  (4 * TILEB)          // Ahi, Alo, Whi, Wlo
#define GSMEM   (MSTAGES * STAGEB)   // 163840 B

#define EPI_TANH 1
#define EPI_STEP 2

__device__ __forceinline__ void load_stage(
    uint32_t sbase, int buf, int k0,
    const __nv_bfloat16* __restrict__ Ahi, const __nv_bfloat16* __restrict__ Alo,
    const __nv_bfloat16* __restrict__ Whi, const __nv_bfloat16* __restrict__ Wlo,
    int bm, int bn, int K, int tid)
{
    uint32_t base = sbase + (uint32_t)buf * STAGEB;
    #pragma unroll
    for (int t = 0; t < 4; t++) {
        const __nv_bfloat16* g = (t == 0) ? Ahi : (t == 1) ? Alo : (t == 2) ? Whi : Wlo;
        int rowbase = (t < 2) ? bm : bn;
        #pragma unroll
        for (int j = 0; j < 2; j++) {
            int c = tid + j * 256;          // 0..511
            int row = c >> 2, c16 = c & 3;  // 128 rows x 4 16B-chunks
            cp_async16(base + (uint32_t)(t * TILEB + row * ROWB + c16 * 16),
                       g + (size_t)(rowbase + row) * K + k0 + c16 * 8);
        }
    }
}

template <int EPI>
__global__ __launch_bounds__(256, 1) void gemm_mma_bf16x3(
    const __nv_bfloat16* __restrict__ Ahi, const __nv_bfloat16* __restrict__ Alo,
    const __nv_bfloat16* __restrict__ Whi, const __nv_bfloat16* __restrict__ Wlo,
    const float* __restrict__ bias, int M, int N, int K,
    float* __restrict__ Cf,
    __nv_bfloat16* __restrict__ Chi, __nv_bfloat16* __restrict__ Clo,
    const float* __restrict__ hprev, const float* __restrict__ xemb, float gamma) {

    extern __shared__ __align__(128) char smem[];
    uint32_t sb = smem_u32(smem);
    int tid = threadIdx.x, wid = tid >> 5, lane = tid & 31;
    int bm = blockIdx.y * 128, bn = blockIdx.x * 128;
    int m0 = (wid >> 2) * 64, n0 = (wid & 3) * 32;

    float acc[4][4][4] = {};

    int nch = K >> 5;
    #pragma unroll
    for (int s = 0; s < MSTAGES - 1; s++) {
        load_stage(sb, s, s << 5, Ahi, Alo, Whi, Wlo, bm, bn, K, tid);
        cp_commit();
    }

    int r16 = lane & 15, kh = lane >> 4;
    int g8 = lane >> 3, l8 = lane & 7;

    for (int i = 0; i < nch; i++) {
        cp_wait<MSTAGES - 2>();
        __syncthreads();

        uint32_t st = sb + (uint32_t)(i & (MSTAGES - 1)) * STAGEB;
        #pragma unroll
        for (int ks = 0; ks < 2; ks++) {
            uint32_t a_hi[4][4], a_lo[4][4], b_hi[2][4], b_lo[2][4];
            #pragma unroll
            for (int mt = 0; mt < 4; mt++) {
                uint32_t ar = st + (uint32_t)((m0 + mt * 16 + r16) * ROWB + ks * 32 + kh * 16);
                ldm_x4(ar, a_hi[mt]);
                ldm_x4(ar + TILEB, a_lo[mt]);
            }
            #pragma unroll
            for (int nh = 0; nh < 2; nh++) {
                uint32_t br = st + 2 * TILEB +
                    (uint32_t)((n0 + nh * 16 + (g8 >> 1) * 8 + l8) * ROWB + ks * 32 + (g8 & 1) * 16);
                ldm_x4(br, b_hi[nh]);
                ldm_x4(br + TILEB, b_lo[nh]);
            }
            #pragma unroll
            for (int mt = 0; mt < 4; mt++) {
                #pragma unroll
                for (int nt = 0; nt < 4; nt++) {
                    const uint32_t* bh = &b_hi[nt >> 1][(nt & 1) * 2];
                    const uint32_t* bl = &b_lo[nt >> 1][(nt & 1) * 2];
                    mma16816(acc[mt][nt], a_hi[mt], bh);   // hi*hi
                    mma16816(acc[mt][nt], a_hi[mt], bl);   // hi*lo
                    mma16816(acc[mt][nt], a_lo[mt], bh);   // lo*hi
                }
            }
        }
        __syncthreads();

        int nxt = i + MSTAGES - 1;
        if (nxt < nch)
            load_stage(sb, nxt & (MSTAGES - 1), nxt << 5, Ahi, Alo, Whi, Wlo, bm, bn, K, tid);
        cp_commit();
    }

    // epilogue from accumulator registers
    int qr = lane >> 2, qc = (lane & 3) * 2;
    #pragma unroll
    for (int mt = 0; mt < 4; mt++) {
        #pragma unroll
        for (int nt = 0; nt < 4; nt++) {
            int c0 = bn + n0 + nt * 8 + qc;
            float2 bz = *(const float2*)(bias + c0);
            #pragma unroll
            for (int h = 0; h < 2; h++) {
                int r = bm + m0 + mt * 16 + qr + h * 8;
                float v0 = acc[mt][nt][h * 2 + 0] + bz.x;
                float v1 = acc[mt][nt][h * 2 + 1] + bz.y;
                size_t idx = (size_t)r * N + c0;
                if (EPI == EPI_TANH) {
                    float t0 = tanhf(v0), t1 = tanhf(v1);
                    __nv_bfloat16 h0 = __float2bfloat16(t0), h1 = __float2bfloat16(t1);
                    __nv_bfloat162 hp; hp.x = h0; hp.y = h1;
                    __nv_bfloat162 lp;
                    lp.x = __float2bfloat16(t0 - __bfloat162float(h0));
                    lp.y = __float2bfloat16(t1 - __bfloat162float(h1));
                    *(__nv_bfloat162*)(Chi + idx) = hp;
                    *(__nv_bfloat162*)(Clo + idx) = lp;
                } else {
                    float2 hp = *(const float2*)(hprev + idx);
                    float2 xe = *(const float2*)(xemb + idx);
                    float2 o;
                    o.x = (1.0f - gamma) * hp.x + gamma * (v0 + xe.x);
                    o.y = (1.0f - gamma) * hp.y + gamma * (v1 + xe.y);
                    *(float2*)(Cf + idx) = o;
                }
            }
        }
    }
}

// ---------------- fp32 SIMT GEMM (embed + head only) ----------------
#define BM 128
#define BN 128
#define BK 8
#define TM 8
#define TN 8

__global__ __launch_bounds__(256, 2) void gemm_f32_bias(
    const float* __restrict__ A, const float* __restrict__ W,
    const float* __restrict__ bias, float* __restrict__ C,
    int M, int N, int K) {

    __shared__ __align__(16) float As[BK][BM];
    __shared__ __align__(16) float Ws[BK][BN];

    int tid = threadIdx.x;
    int bm = blockIdx.y * BM, bn = blockIdx.x * BN;
    const float* Ablk = A + (size_t)bm * K;
    const float* Wblk = W + (size_t)bn * K;

    int lrow = tid >> 1;
    int lcol = (tid & 1) * 4;
    int ty = tid >> 4, tx = tid & 15;

    float acc[TM][TN] = {};

    for (int k0 = 0; k0 < K; k0 += BK) {
        float4 a4 = *reinterpret_cast<const float4*>(Ablk + (size_t)lrow * K + k0 + lcol);
        float4 w4 = *reinterpret_cast<const float4*>(Wblk + (size_t)lrow * K + k0 + lcol);
        As[lcol + 0][lrow] = a4.x; As[lcol + 1][lrow] = a4.y;
        As[lcol + 2][lrow] = a4.z; As[lcol + 3][lrow] = a4.w;
        Ws[lcol + 0][lrow] = w4.x; Ws[lcol + 1][lrow] = w4.y;
        Ws[lcol + 2][lrow] = w4.z; Ws[lcol + 3][lrow] = w4.w;
        __syncthreads();
        #pragma unroll
        for (int k = 0; k < BK; k++) {
            float4 a0 = *reinterpret_cast<const float4*>(&As[k][ty * TM]);
            float4 a1 = *reinterpret_cast<const float4*>(&As[k][ty * TM + 4]);
            float4 w0 = *reinterpret_cast<const float4*>(&Ws[k][tx * TN]);
            float4 w1 = *reinterpret_cast<const float4*>(&Ws[k][tx * TN + 4]);
            float ra[TM] = {a0.x, a0.y, a0.z, a0.w, a1.x, a1.y, a1.z, a1.w};
            float rw[TN] = {w0.x, w0.y, w0.z, w0.w, w1.x, w1.y, w1.z, w1.w};
            #pragma unroll
            for (int i = 0; i < TM; i++)
                #pragma unroll
                for (int j = 0; j < TN; j++)
                    acc[i][j] += ra[i] * rw[j];
        }
        __syncthreads();
    }

    #pragma unroll
    for (int i = 0; i < TM; i++) {
        int m = bm + ty * TM + i;
        #pragma unroll
        for (int j = 0; j < TN; j++) {
            int n = bn + tx * TN + j;
            C[(size_t)m * N + n] = acc[i][j] + bias[n];
        }
    }
}

// ---------------- host-side helpers ----------------
static void spectral_sigma(const float* W, int R, int C,
                           float* u, float* v, float* t, float* sig) {
    float v0 = 1.0f / sqrtf((float)C);
    init_vec_kernel<<<(C + 255) / 256, 256>>>(v, C, v0);
    for (int it = 0; it < 15; it++) {
        matvec_rows<<<R, 256>>>(W, v, u, C);
        normalize_vec<<<1, 1024>>>(u, R);
        init_vec_kernel<<<(C + 255) / 256, 256>>>(v, C, 0.f);
        matvec_cols<<<dim3(C / 32, 8), 256>>>(W, u, v, R, C);
        normalize_vec<<<1, 1024>>>(v, C);
    }
    matvec_rows<<<R, 256>>>(W, v, t, C);
    dot_kernel<<<1, 1024>>>(u, t, sig, R);
}

extern "C" void kernel_launch(void* const* d_in, const int* in_sizes, int n_in,
                              void* d_out, int out_size) {
    const float* x       = (const float*)d_in[0];
    const float* embed_w = (const float*)d_in[1];
    const float* embed_b = (const float*)d_in[2];
    const float* W1      = (const float*)d_in[3];
    const float* b1      = (const float*)d_in[4];
    const float* W2      = (const float*)d_in[5];
    const float* b2      = (const float*)d_in[6];
    const float* ln_g    = (const float*)d_in[7];
    const float* ln_b    = (const float*)d_in[8];
    const float* head_w  = (const float*)d_in[9];
    const float* head_b  = (const float*)d_in[10];
    float* out = (float*)d_out;

    float *p_xemb, *p_hA, *p_hB, *p_u, *p_v, *p_t, *p_sig;
    __nv_bfloat16 *p_W1hi, *p_W1lo, *p_W2hi, *p_W2lo, *p_hnhi, *p_hnlo, *p_hidhi, *p_hidlo;
    cudaGetSymbolAddress((void**)&p_xemb, g_xemb);
    cudaGetSymbolAddress((void**)&p_hA, g_hA);
    cudaGetSymbolAddress((void**)&p_hB, g_hB);
    cudaGetSymbolAddress((void**)&p_u, g_u);
    cudaGetSymbolAddress((void**)&p_v, g_v);
    cudaGetSymbolAddress((void**)&p_t, g_t);
    cudaGetSymbolAddress((void**)&p_sig, g_sig);
    cudaGetSymbolAddress((void**)&p_W1hi, g_W1hi);
    cudaGetSymbolAddress((void**)&p_W1lo, g_W1lo);
    cudaGetSymbolAddress((void**)&p_W2hi, g_W2hi);
    cudaGetSymbolAddress((void**)&p_W2lo, g_W2lo);
    cudaGetSymbolAddress((void**)&p_hnhi, g_hnhi);
    cudaGetSymbolAddress((void**)&p_hnlo, g_hnlo);
    cudaGetSymbolAddress((void**)&p_hidhi, g_hidhi);
    cudaGetSymbolAddress((void**)&p_hidlo, g_hidlo);

    cudaFuncSetAttribute(gemm_mma_bf16x3<EPI_TANH>,
                         cudaFuncAttributeMaxDynamicSharedMemorySize, GSMEM);
    cudaFuncSetAttribute(gemm_mma_bf16x3<EPI_STEP>,
                         cudaFuncAttributeMaxDynamicSharedMemorySize, GSMEM);

    // spectral sigma + bf16 hi/lo split of W1n, W2n
    spectral_sigma(W1, DFF, DH, p_u, p_v, p_t, p_sig);
    scale_split<<<2048, 256>>>(W1, p_sig, p_W1hi, p_W1lo, (size_t)DFF * DH);
    spectral_sigma(W2, DH, DFF, p_u, p_v, p_t, p_sig);
    scale_split<<<2048, 256>>>(W2, p_sig, p_W2hi, p_W2lo, (size_t)DH * DFF);

    // x_emb = x @ embed_w^T + embed_b  (fp32 SIMT)
    gemm_f32_bias<<<dim3(DH / BN, B_ / BM), 256>>>(x, embed_w, embed_b, p_xemb, B_, DH, DIN);

    // h0 = x_emb
    cudaMemcpyAsync(p_hA, p_xemb, (size_t)B_ * DH * sizeof(float), cudaMemcpyDeviceToDevice);

    float* hc = p_hA;
    float* hx = p_hB;
    for (int s = 0; s < STEPS; s++) {
        layernorm_split<<<B_, 256>>>(hc, ln_g, ln_b, p_hnhi, p_hnlo);
        gemm_mma_bf16x3<EPI_TANH><<<dim3(DFF / 128, B_ / 128), 256, GSMEM>>>(
            p_hnhi, p_hnlo, p_W1hi, p_W1lo, b1, B_, DFF, DH,
            nullptr, p_hidhi, p_hidlo, nullptr, nullptr, 0.f);
        gemm_mma_bf16x3<EPI_STEP><<<dim3(DH / 128, B_ / 128), 256, GSMEM>>>(
            p_hidhi, p_hidlo, p_W2hi, p_W2lo, b2, B_, DH, DFF,
            hx, nullptr, nullptr, hc, p_xemb, GAMMA_F);
        float* tmp = hc; hc = hx; hx = tmp;
    }

    // out = h @ head_w^T + head_b (fp32 SIMT)
    gemm_f32_bias<<<dim3(DOUT / BN, B_ / BM), 256>>>(hc, head_w, head_b, out, B_, DOUT, DH);
}

// round 5
// speedup vs baseline: 2.6987x; 1.0543x over previous
#include <cuda_runtime.h>
#include <cuda_bf16.h>
#include <math.h>
#include <cstddef>
#include <cstdint>

// ---------------- problem constants ----------------
#define B_    4096
#define DIN   512
#define DH    1024
#define DOUT  256
#define DFF   4096
#define STEPS 30
#define LN_EPSF 1e-5f
#define GAMMA_F 0.17677669529663687f   // 0.5*sqrt(64/512)
#define NSM   148

// ---------------- device scratch (no allocations allowed) ----------------
__device__ float g_xemb[(size_t)B_ * DH];
__device__ float g_hA[(size_t)B_ * DH];
__device__ float g_hB[(size_t)B_ * DH];
__device__ __nv_bfloat16 g_W1hi[(size_t)DFF * DH];
__device__ __nv_bfloat16 g_W1lo[(size_t)DFF * DH];
__device__ __nv_bfloat16 g_W2hi[(size_t)DH * DFF];
__device__ __nv_bfloat16 g_W2lo[(size_t)DH * DFF];
__device__ __nv_bfloat16 g_hnhi[(size_t)B_ * DH];
__device__ __nv_bfloat16 g_hnlo[(size_t)B_ * DH];
__device__ __nv_bfloat16 g_hidhi[(size_t)B_ * DFF];
__device__ __nv_bfloat16 g_hidlo[(size_t)B_ * DFF];
__device__ float g_u[4096];
__device__ float g_v[4096];
__device__ float g_t[4096];
__device__ float g_sig[2];

// ---------------- low-level helpers (plain sm_80+ features only) ----------------
__device__ __forceinline__ uint32_t smem_u32(const void* p) {
    uint32_t a;
    asm("{ .reg .u64 t; cvta.to.shared.u64 t, %1; cvt.u32.u64 %0, t; }" : "=r"(a) : "l"(p));
    return a;
}
__device__ __forceinline__ void cp_async16(uint32_t dst, const void* src) {
    asm volatile("cp.async.cg.shared.global [%0], [%1], 16;" :: "r"(dst), "l"(src) : "memory");
}
__device__ __forceinline__ void cp_commit() {
    asm volatile("cp.async.commit_group;" ::: "memory");
}
template<int N> __device__ __forceinline__ void cp_wait() {
    asm volatile("cp.async.wait_group %0;" :: "n"(N) : "memory");
}
__device__ __forceinline__ void ldm_x4(uint32_t addr, uint32_t* r) {
    asm volatile("ldmatrix.sync.aligned.m8n8.x4.shared.b16 {%0,%1,%2,%3}, [%4];"
        : "=r"(r[0]), "=r"(r[1]), "=r"(r[2]), "=r"(r[3]) : "r"(addr));
}
__device__ __forceinline__ void mma16816(float* d, const uint32_t* a, const uint32_t* b) {
    asm volatile("mma.sync.aligned.m16n8k16.row.col.f32.bf16.bf16.f32 "
        "{%0,%1,%2,%3}, {%4,%5,%6,%7}, {%8,%9}, {%0,%1,%2,%3};"
        : "+f"(d[0]), "+f"(d[1]), "+f"(d[2]), "+f"(d[3])
        : "r"(a[0]), "r"(a[1]), "r"(a[2]), "r"(a[3]), "r"(b[0]), "r"(b[1]));
}

// ---------------- small kernels: spectral norm ----------------
__global__ void init_vec_kernel(float* v, int n, float val) {
    int i = blockIdx.x * blockDim.x + threadIdx.x;
    if (i < n) v[i] = val;
}

__global__ void matvec_rows(const float* __restrict__ W, const float* __restrict__ v,
                            float* __restrict__ y, int C) {
    int row = blockIdx.x;
    const float* Wr = W + (size_t)row * C;
    float acc = 0.f;
    for (int j = threadIdx.x; j < C; j += 256) acc += Wr[j] * v[j];
    __shared__ float sm[8];
    #pragma unroll
    for (int o = 16; o > 0; o >>= 1) acc += __shfl_down_sync(0xffffffffu, acc, o);
    if ((threadIdx.x & 31) == 0) sm[threadIdx.x >> 5] = acc;
    __syncthreads();
    if (threadIdx.x < 8) {
        float a = sm[threadIdx.x];
        #pragma unroll
        for (int o = 4; o > 0; o >>= 1) a += __shfl_down_sync(0xffu, a, o);
        if (threadIdx.x == 0) y[row] = a;
    }
}

// z[col] += partial dot(W[:,col], u); grid (C/32, 8); z must be zeroed first
__global__ void matvec_cols(const float* __restrict__ W, const float* __restrict__ u,
                            float* __restrict__ z, int R, int C) {
    int lane = threadIdx.x & 31;
    int rp   = threadIdx.x >> 5;
    int col  = blockIdx.x * 32 + lane;
    int rchunk = R >> 3;
    int r0 = blockIdx.y * rchunk;
    int r1 = r0 + rchunk;
    float acc = 0.f;
    for (int i = r0 + rp; i < r1; i += 8) acc += W[(size_t)i * C + col] * u[i];
    __shared__ float sm[8][33];
    sm[rp][lane] = acc;
    __syncthreads();
    if (rp == 0) {
        float a = 0.f;
        #pragma unroll
        for (int r = 0; r < 8; r++) a += sm[r][lane];
        atomicAdd(&z[col], a);
    }
}

__global__ void normalize_vec(float* v, int n) {
    __shared__ float sm[32];
    __shared__ float s_inv;
    float acc = 0.f;
    for (int i = threadIdx.x; i < n; i += 1024) { float x = v[i]; acc += x * x; }
    #pragma unroll
    for (int o = 16; o > 0; o >>= 1) acc += __shfl_down_sync(0xffffffffu, acc, o);
    if ((threadIdx.x & 31) == 0) sm[threadIdx.x >> 5] = acc;
    __syncthreads();
    if (threadIdx.x < 32) {
        float a = sm[threadIdx.x];
        #pragma unroll
        for (int o = 16; o > 0; o >>= 1) a += __shfl_down_sync(0xffffffffu, a, o);
        if (threadIdx.x == 0) s_inv = 1.0f / (sqrtf(a) + 1e-12f);
    }
    __syncthreads();
    float inv = s_inv;
    for (int i = threadIdx.x; i < n; i += 1024) v[i] *= inv;
}

__global__ void dot_kernel(const float* __restrict__ a, const float* __restrict__ b,
                           float* __restrict__ out, int n) {
    __shared__ float sm[32];
    float acc = 0.f;
    for (int i = threadIdx.x; i < n; i += 1024) acc += a[i] * b[i];
    #pragma unroll
    for (int o = 16; o > 0; o >>= 1) acc += __shfl_down_sync(0xffffffffu, acc, o);
    if ((threadIdx.x & 31) == 0) sm[threadIdx.x >> 5] = acc;
    __syncthreads();
    if (threadIdx.x < 32) {
        float a2 = sm[threadIdx.x];
        #pragma unroll
        for (int o = 16; o > 0; o >>= 1) a2 += __shfl_down_sync(0xffffffffu, a2, o);
        if (threadIdx.x == 0) out[0] = a2;
    }
}

// Wn = W / sigma, split into bf16 hi/lo pair
__global__ void scale_split(const float* __restrict__ W, const float* __restrict__ sig,
                            __nv_bfloat16* __restrict__ hi, __nv_bfloat16* __restrict__ lo,
                            size_t n) {
    float inv = 1.0f / sig[0];
    size_t stride = (size_t)gridDim.x * blockDim.x;
    for (size_t i = (size_t)blockIdx.x * blockDim.x + threadIdx.x; i < n; i += stride) {
        float w = W[i] * inv;
        __nv_bfloat16 h = __float2bfloat16(w);
        hi[i] = h;
        lo[i] = __float2bfloat16(w - __bfloat162float(h));
    }
}

// ---------------- layernorm: fp32 in, bf16 hi/lo out ----------------
__global__ void layernorm_split(const float* __restrict__ h,
                                const float* __restrict__ g, const float* __restrict__ b,
                                __nv_bfloat16* __restrict__ ohi, __nv_bfloat16* __restrict__ olo) {
    int row = blockIdx.x;
    const float* hr = h + (size_t)row * DH;
    float s = 0.f, ss = 0.f;
    float xl[4];
    #pragma unroll
    for (int t = 0; t < 4; t++) {
        float x = hr[threadIdx.x + t * 256];
        xl[t] = x; s += x; ss += x * x;
    }
    __shared__ float sm1[8], sm2[8];
    #pragma unroll
    for (int o = 16; o > 0; o >>= 1) {
        s  += __shfl_down_sync(0xffffffffu, s, o);
        ss += __shfl_down_sync(0xffffffffu, ss, o);
    }
    if ((threadIdx.x & 31) == 0) { sm1[threadIdx.x >> 5] = s; sm2[threadIdx.x >> 5] = ss; }
    __syncthreads();
    __shared__ float s_mu, s_inv;
    if (threadIdx.x < 8) {
        float a = sm1[threadIdx.x], c = sm2[threadIdx.x];
        #pragma unroll
        for (int o = 4; o > 0; o >>= 1) {
            a += __shfl_down_sync(0xffu, a, o);
            c += __shfl_down_sync(0xffu, c, o);
        }
        if (threadIdx.x == 0) {
            float mu  = a * (1.0f / DH);
            float var = c * (1.0f / DH) - mu * mu;
            s_mu = mu; s_inv = rsqrtf(var + LN_EPSF);
        }
    }
    __syncthreads();
    float mu = s_mu, inv = s_inv;
    #pragma unroll
    for (int t = 0; t < 4; t++) {
        int j = threadIdx.x + t * 256;
        float y = (xl[t] - mu) * inv * g[j] + b[j];
        __nv_bfloat16 hh = __float2bfloat16(y);
        size_t idx = (size_t)row * DH + j;
        ohi[idx] = hh;
        olo[idx] = __float2bfloat16(y - __bfloat162float(hh));
    }
}

// ---------------- HMMA bf16x3-split persistent GEMM ----------------
// C[M,N] = (Ahi+Alo)[M,K] @ ((Whi+Wlo)[N,K])^T, 3 first-order terms.
// CTA tile 128x128, 8 warps (2x4), warp tile 64x32 = 4x4 m16n8k16 frags.
// BK=32, 4-stage cp.async pipeline, persistent CTAs over flattened tile loop.
#define MSTAGES 4
#define ROWB    80
#define TILEB   (128 * ROWB)         // 10240 B per 128x32 bf16 tile
#define STAGEB  (4 * TILEB)          // Ahi, Alo, Whi, Wlo
#define GSMEM   (MSTAGES * STAGEB)   // 163840 B

#define EPI_TANH 1
#define EPI_STEP 2

__device__ __forceinline__ void load_stage(
    uint32_t sbase, int buf, int k0,
    const __nv_bfloat16* __restrict__ Ahi, const __nv_bfloat16* __restrict__ Alo,
    const __nv_bfloat16* __restrict__ Whi, const __nv_bfloat16* __restrict__ Wlo,
    int bm, int bn, int K, int tid)
{
    uint32_t base = sbase + (uint32_t)buf * STAGEB;
    #pragma unroll
    for (int t = 0; t < 4; t++) {
        const __nv_bfloat16* g = (t == 0) ? Ahi : (t == 1) ? Alo : (t == 2) ? Whi : Wlo;
        int rowbase = (t < 2) ? bm : bn;
        #pragma unroll
        for (int j = 0; j < 2; j++) {
            int c = tid + j * 256;          // 0..511
            int row = c >> 2, c16 = c & 3;  // 128 rows x 4 16B-chunks
            cp_async16(base + (uint32_t)(t * TILEB + row * ROWB + c16 * 16),
                       g + (size_t)(rowbase + row) * K + k0 + c16 * 8);
        }
    }
}

template <int EPI>
__global__ __launch_bounds__(256, 1) void gemm_mma_bf16x3(
    const __nv_bfloat16* __restrict__ Ahi, const __nv_bfloat16* __restrict__ Alo,
    const __nv_bfloat16* __restrict__ Whi, const __nv_bfloat16* __restrict__ Wlo,
    const float* __restrict__ bias, int N, int K, int ntiles, int nx,
    float* __restrict__ Cf,
    __nv_bfloat16* __restrict__ Chi, __nv_bfloat16* __restrict__ Clo,
    const float* __restrict__ hprev, const float* __restrict__ xemb, float gamma) {

    extern __shared__ __align__(128) char smem[];
    uint32_t sb = smem_u32(smem);
    int tid = threadIdx.x, wid = tid >> 5, lane = tid & 31;
    int m0 = (wid >> 2) * 64, n0 = (wid & 3) * 32;
    int r16 = lane & 15, kh = lane >> 4;
    int g8 = lane >> 3, l8 = lane & 7;
    int qr = lane >> 2, qc = (lane & 3) * 2;
    const int nch = K >> 5;

    for (int tile = blockIdx.x; tile < ntiles; tile += gridDim.x) {
        int bm = (tile / nx) * 128, bn = (tile % nx) * 128;

        float acc[4][4][4] = {};

        #pragma unroll
        for (int s = 0; s < MSTAGES - 1; s++) {
            load_stage(sb, s, s << 5, Ahi, Alo, Whi, Wlo, bm, bn, K, tid);
            cp_commit();
        }

        for (int i = 0; i < nch; i++) {
            cp_wait<MSTAGES - 2>();
            __syncthreads();

            uint32_t st = sb + (uint32_t)(i & (MSTAGES - 1)) * STAGEB;
            #pragma unroll
            for (int ks = 0; ks < 2; ks++) {
                uint32_t a_hi[4][4], a_lo[4][4], b_hi[2][4], b_lo[2][4];
                #pragma unroll
                for (int mt = 0; mt < 4; mt++) {
                    uint32_t ar = st + (uint32_t)((m0 + mt * 16 + r16) * ROWB + ks * 32 + kh * 16);
                    ldm_x4(ar, a_hi[mt]);
                    ldm_x4(ar + TILEB, a_lo[mt]);
                }
                #pragma unroll
                for (int nh = 0; nh < 2; nh++) {
                    uint32_t br = st + 2 * TILEB +
                        (uint32_t)((n0 + nh * 16 + (g8 >> 1) * 8 + l8) * ROWB + ks * 32 + (g8 & 1) * 16);
                    ldm_x4(br, b_hi[nh]);
                    ldm_x4(br + TILEB, b_lo[nh]);
                }
                // term-outer ordering: 16 independent MMAs between RAW pairs
                #pragma unroll
                for (int mt = 0; mt < 4; mt++)
                    #pragma unroll
                    for (int nt = 0; nt < 4; nt++)
                        mma16816(acc[mt][nt], a_hi[mt], &b_hi[nt >> 1][(nt & 1) * 2]);
                #pragma unroll
                for (int mt = 0; mt < 4; mt++)
                    #pragma unroll
                    for (int nt = 0; nt < 4; nt++)
                        mma16816(acc[mt][nt], a_hi[mt], &b_lo[nt >> 1][(nt & 1) * 2]);
                #pragma unroll
                for (int mt = 0; mt < 4; mt++)
                    #pragma unroll
                    for (int nt = 0; nt < 4; nt++)
                        mma16816(acc[mt][nt], a_lo[mt], &b_hi[nt >> 1][(nt & 1) * 2]);
            }

            int nxt = i + MSTAGES - 1;
            if (nxt < nch)
                load_stage(sb, nxt & (MSTAGES - 1), nxt << 5, Ahi, Alo, Whi, Wlo, bm, bn, K, tid);
            cp_commit();
        }

        // epilogue from accumulator registers
        #pragma unroll
        for (int mt = 0; mt < 4; mt++) {
            #pragma unroll
            for (int nt = 0; nt < 4; nt++) {
                int c0 = bn + n0 + nt * 8 + qc;
                float2 bz = *(const float2*)(bias + c0);
                #pragma unroll
                for (int h = 0; h < 2; h++) {
                    int r = bm + m0 + mt * 16 + qr + h * 8;
                    float v0 = acc[mt][nt][h * 2 + 0] + bz.x;
                    float v1 = acc[mt][nt][h * 2 + 1] + bz.y;
                    size_t idx = (size_t)r * N + c0;
                    if (EPI == EPI_TANH) {
                        float t0 = tanhf(v0), t1 = tanhf(v1);
                        __nv_bfloat16 h0 = __float2bfloat16(t0), h1 = __float2bfloat16(t1);
                        __nv_bfloat162 hp; hp.x = h0; hp.y = h1;
                        __nv_bfloat162 lp;
                        lp.x = __float2bfloat16(t0 - __bfloat162float(h0));
                        lp.y = __float2bfloat16(t1 - __bfloat162float(h1));
                        *(__nv_bfloat162*)(Chi + idx) = hp;
                        *(__nv_bfloat162*)(Clo + idx) = lp;
                    } else {
                        float2 hp = *(const float2*)(hprev + idx);
                        float2 xe = *(const float2*)(xemb + idx);
                        float2 o;
                        o.x = (1.0f - gamma) * hp.x + gamma * (v0 + xe.x);
                        o.y = (1.0f - gamma) * hp.y + gamma * (v1 + xe.y);
                        *(float2*)(Cf + idx) = o;
                    }
                }
            }
        }
        __syncthreads();   // protect smem buffers before next tile's prologue
    }
}

// ---------------- fp32 SIMT GEMM (embed + head only) ----------------
#define BM 128
#define BN 128
#define BK 8
#define TM 8
#define TN 8

__global__ __launch_bounds__(256, 2) void gemm_f32_bias(
    const float* __restrict__ A, const float* __restrict__ W,
    const float* __restrict__ bias, float* __restrict__ C,
    int M, int N, int K) {

    __shared__ __align__(16) float As[BK][BM];
    __shared__ __align__(16) float Ws[BK][BN];

    int tid = threadIdx.x;
    int bm = blockIdx.y * BM, bn = blockIdx.x * BN;
    const float* Ablk = A + (size_t)bm * K;
    const float* Wblk = W + (size_t)bn * K;

    int lrow = tid >> 1;
    int lcol = (tid & 1) * 4;
    int ty = tid >> 4, tx = tid & 15;

    float acc[TM][TN] = {};

    for (int k0 = 0; k0 < K; k0 += BK) {
        float4 a4 = *reinterpret_cast<const float4*>(Ablk + (size_t)lrow * K + k0 + lcol);
        float4 w4 = *reinterpret_cast<const float4*>(Wblk + (size_t)lrow * K + k0 + lcol);
        As[lcol + 0][lrow] = a4.x; As[lcol + 1][lrow] = a4.y;
        As[lcol + 2][lrow] = a4.z; As[lcol + 3][lrow] = a4.w;
        Ws[lcol + 0][lrow] = w4.x; Ws[lcol + 1][lrow] = w4.y;
        Ws[lcol + 2][lrow] = w4.z; Ws[lcol + 3][lrow] = w4.w;
        __syncthreads();
        #pragma unroll
        for (int k = 0; k < BK; k++) {
            float4 a0 = *reinterpret_cast<const float4*>(&As[k][ty * TM]);
            float4 a1 = *reinterpret_cast<const float4*>(&As[k][ty * TM + 4]);
            float4 w0 = *reinterpret_cast<const float4*>(&Ws[k][tx * TN]);
            float4 w1 = *reinterpret_cast<const float4*>(&Ws[k][tx * TN + 4]);
            float ra[TM] = {a0.x, a0.y, a0.z, a0.w, a1.x, a1.y, a1.z, a1.w};
            float rw[TN] = {w0.x, w0.y, w0.z, w0.w, w1.x, w1.y, w1.z, w1.w};
            #pragma unroll
            for (int i = 0; i < TM; i++)
                #pragma unroll
                for (int j = 0; j < TN; j++)
                    acc[i][j] += ra[i] * rw[j];
        }
        __syncthreads();
    }

    #pragma unroll
    for (int i = 0; i < TM; i++) {
        int m = bm + ty * TM + i;
        #pragma unroll
        for (int j = 0; j < TN; j++) {
            int n = bn + tx * TN + j;
            C[(size_t)m * N + n] = acc[i][j] + bias[n];
        }
    }
}

// ---------------- host-side helpers ----------------
static void spectral_sigma(const float* W, int R, int C,
                           float* u, float* v, float* t, float* sig) {
    float v0 = 1.0f / sqrtf((float)C);
    init_vec_kernel<<<(C + 255) / 256, 256>>>(v, C, v0);
    for (int it = 0; it < 15; it++) {
        matvec_rows<<<R, 256>>>(W, v, u, C);
        normalize_vec<<<1, 1024>>>(u, R);
        init_vec_kernel<<<(C + 255) / 256, 256>>>(v, C, 0.f);
        matvec_cols<<<dim3(C / 32, 8), 256>>>(W, u, v, R, C);
        normalize_vec<<<1, 1024>>>(v, C);
    }
    matvec_rows<<<R, 256>>>(W, v, t, C);
    dot_kernel<<<1, 1024>>>(u, t, sig, R);
}

extern "C" void kernel_launch(void* const* d_in, const int* in_sizes, int n_in,
                              void* d_out, int out_size) {
    const float* x       = (const float*)d_in[0];
    const float* embed_w = (const float*)d_in[1];
    const float* embed_b = (const float*)d_in[2];
    const float* W1      = (const float*)d_in[3];
    const float* b1      = (const float*)d_in[4];
    const float* W2      = (const float*)d_in[5];
    const float* b2      = (const float*)d_in[6];
    const float* ln_g    = (const float*)d_in[7];
    const float* ln_b    = (const float*)d_in[8];
    const float* head_w  = (const float*)d_in[9];
    const float* head_b  = (const float*)d_in[10];
    float* out = (float*)d_out;

    float *p_xemb, *p_hA, *p_hB, *p_u, *p_v, *p_t, *p_sig;
    __nv_bfloat16 *p_W1hi, *p_W1lo, *p_W2hi, *p_W2lo, *p_hnhi, *p_hnlo, *p_hidhi, *p_hidlo;
    cudaGetSymbolAddress((void**)&p_xemb, g_xemb);
    cudaGetSymbolAddress((void**)&p_hA, g_hA);
    cudaGetSymbolAddress((void**)&p_hB, g_hB);
    cudaGetSymbolAddress((void**)&p_u, g_u);
    cudaGetSymbolAddress((void**)&p_v, g_v);
    cudaGetSymbolAddress((void**)&p_t, g_t);
    cudaGetSymbolAddress((void**)&p_sig, g_sig);
    cudaGetSymbolAddress((void**)&p_W1hi, g_W1hi);
    cudaGetSymbolAddress((void**)&p_W1lo, g_W1lo);
    cudaGetSymbolAddress((void**)&p_W2hi, g_W2hi);
    cudaGetSymbolAddress((void**)&p_W2lo, g_W2lo);
    cudaGetSymbolAddress((void**)&p_hnhi, g_hnhi);
    cudaGetSymbolAddress((void**)&p_hnlo, g_hnlo);
    cudaGetSymbolAddress((void**)&p_hidhi, g_hidhi);
    cudaGetSymbolAddress((void**)&p_hidlo, g_hidlo);

    cudaFuncSetAttribute(gemm_mma_bf16x3<EPI_TANH>,
                         cudaFuncAttributeMaxDynamicSharedMemorySize, GSMEM);
    cudaFuncSetAttribute(gemm_mma_bf16x3<EPI_STEP>,
                         cudaFuncAttributeMaxDynamicSharedMemorySize, GSMEM);

    // spectral sigma + bf16 hi/lo split of W1n, W2n
    spectral_sigma(W1, DFF, DH, p_u, p_v, p_t, p_sig);
    scale_split<<<2048, 256>>>(W1, p_sig, p_W1hi, p_W1lo, (size_t)DFF * DH);
    spectral_sigma(W2, DH, DFF, p_u, p_v, p_t, p_sig);
    scale_split<<<2048, 256>>>(W2, p_sig, p_W2hi, p_W2lo, (size_t)DH * DFF);

    // x_emb = x @ embed_w^T + embed_b  (fp32 SIMT)
    gemm_f32_bias<<<dim3(DH / BN, B_ / BM), 256>>>(x, embed_w, embed_b, p_xemb, B_, DH, DIN);

    // h0 = x_emb
    cudaMemcpyAsync(p_hA, p_xemb, (size_t)B_ * DH * sizeof(float), cudaMemcpyDeviceToDevice);

    const int nt1 = (B_ / 128) * (DFF / 128);   // 1024 tiles, nx=32
    const int nt2 = (B_ / 128) * (DH / 128);    // 256 tiles,  nx=8

    float* hc = p_hA;
    float* hx = p_hB;
    for (int s = 0; s < STEPS; s++) {
        layernorm_split<<<B_, 256>>>(hc, ln_g, ln_b, p_hnhi, p_hnlo);
        gemm_mma_bf16x3<EPI_TANH><<<NSM, 256, GSMEM>>>(
            p_hnhi, p_hnlo, p_W1hi, p_W1lo, b1, DFF, DH, nt1, DFF / 128,
            nullptr, p_hidhi, p_hidlo, nullptr, nullptr, 0.f);
        gemm_mma_bf16x3<EPI_STEP><<<NSM, 256, GSMEM>>>(
            p_hidhi, p_hidlo, p_W2hi, p_W2lo, b2, DH, DFF, nt2, DH / 128,
            hx, nullptr, nullptr, hc, p_xemb, GAMMA_F);
        float* tmp = hc; hc = hx; hx = tmp;
    }

    // out = h @ head_w^T + head_b (fp32 SIMT)
    gemm_f32_bias<<<dim3(DOUT / BN, B_ / BM), 256>>>(hc, head_w, head_b, out, B_, DOUT, DH);
}

// round 6
// speedup vs baseline: 2.8674x; 1.0625x over previous
#include <cuda_runtime.h>
#include <cuda_bf16.h>
#include <math.h>
#include <cstddef>
#include <cstdint>

// ---------------- problem constants ----------------
#define B_    4096
#define DIN   512
#define DH    1024
#define DOUT  256
#define DFF   4096
#define STEPS 30
#define LN_EPSF 1e-5f
#define GAMMA_F 0.17677669529663687f   // 0.5*sqrt(64/512)
#define NSM   148

// ---------------- device scratch (no allocations allowed) ----------------
__device__ float g_xemb[(size_t)B_ * DH];
__device__ float g_hA[(size_t)B_ * DH];
__device__ float g_hB[(size_t)B_ * DH];
__device__ __nv_bfloat16 g_W1hi[(size_t)DFF * DH];
__device__ __nv_bfloat16 g_W1lo[(size_t)DFF * DH];
__device__ __nv_bfloat16 g_W2hi[(size_t)DH * DFF];
__device__ __nv_bfloat16 g_W2lo[(size_t)DH * DFF];
__device__ __nv_bfloat16 g_hnhi[(size_t)B_ * DH];
__device__ __nv_bfloat16 g_hnlo[(size_t)B_ * DH];
__device__ __nv_bfloat16 g_hidhi[(size_t)B_ * DFF];
__device__ __nv_bfloat16 g_hidlo[(size_t)B_ * DFF];
__device__ float g_u[4096];
__device__ float g_v[4096];
__device__ float g_t[4096];
__device__ float g_sig[2];

// ---------------- low-level helpers (plain sm_80+ features only) ----------------
__device__ __forceinline__ uint32_t smem_u32(const void* p) {
    uint32_t a;
    asm("{ .reg .u64 t; cvta.to.shared.u64 t, %1; cvt.u32.u64 %0, t; }" : "=r"(a) : "l"(p));
    return a;
}
__device__ __forceinline__ void cp_async16(uint32_t dst, const void* src) {
    asm volatile("cp.async.cg.shared.global [%0], [%1], 16;" :: "r"(dst), "l"(src) : "memory");
}
__device__ __forceinline__ void cp_commit() {
    asm volatile("cp.async.commit_group;" ::: "memory");
}
template<int N> __device__ __forceinline__ void cp_wait() {
    asm volatile("cp.async.wait_group %0;" :: "n"(N) : "memory");
}
__device__ __forceinline__ void ldm_x4(uint32_t addr, uint32_t* r) {
    asm volatile("ldmatrix.sync.aligned.m8n8.x4.shared.b16 {%0,%1,%2,%3}, [%4];"
        : "=r"(r[0]), "=r"(r[1]), "=r"(r[2]), "=r"(r[3]) : "r"(addr));
}
__device__ __forceinline__ void mma16816(float* d, const uint32_t* a, const uint32_t* b) {
    asm volatile("mma.sync.aligned.m16n8k16.row.col.f32.bf16.bf16.f32 "
        "{%0,%1,%2,%3}, {%4,%5,%6,%7}, {%8,%9}, {%0,%1,%2,%3};"
        : "+f"(d[0]), "+f"(d[1]), "+f"(d[2]), "+f"(d[3])
        : "r"(a[0]), "r"(a[1]), "r"(a[2]), "r"(a[3]), "r"(b[0]), "r"(b[1]));
}

// ---------------- small kernels: spectral norm ----------------
__global__ void init_vec_kernel(float* v, int n, float val) {
    int i = blockIdx.x * blockDim.x + threadIdx.x;
    if (i < n) v[i] = val;
}

__global__ void matvec_rows(const float* __restrict__ W, const float* __restrict__ v,
                            float* __restrict__ y, int C) {
    int row = blockIdx.x;
    const float* Wr = W + (size_t)row * C;
    float acc = 0.f;
    for (int j = threadIdx.x; j < C; j += 256) acc += Wr[j] * v[j];
    __shared__ float sm[8];
    #pragma unroll
    for (int o = 16; o > 0; o >>= 1) acc += __shfl_down_sync(0xffffffffu, acc, o);
    if ((threadIdx.x & 31) == 0) sm[threadIdx.x >> 5] = acc;
    __syncthreads();
    if (threadIdx.x < 8) {
        float a = sm[threadIdx.x];
        #pragma unroll
        for (int o = 4; o > 0; o >>= 1) a += __shfl_down_sync(0xffu, a, o);
        if (threadIdx.x == 0) y[row] = a;
    }
}

// z[col] += partial dot(W[:,col], u); grid (C/32, 8); z must be zeroed first
__global__ void matvec_cols(const float* __restrict__ W, const float* __restrict__ u,
                            float* __restrict__ z, int R, int C) {
    int lane = threadIdx.x & 31;
    int rp   = threadIdx.x >> 5;
    int col  = blockIdx.x * 32 + lane;
    int rchunk = R >> 3;
    int r0 = blockIdx.y * rchunk;
    int r1 = r0 + rchunk;
    float acc = 0.f;
    for (int i = r0 + rp; i < r1; i += 8) acc += W[(size_t)i * C + col] * u[i];
    __shared__ float sm[8][33];
    sm[rp][lane] = acc;
    __syncthreads();
    if (rp == 0) {
        float a = 0.f;
        #pragma unroll
        for (int r = 0; r < 8; r++) a += sm[r][lane];
        atomicAdd(&z[col], a);
    }
}

__global__ void normalize_vec(float* v, int n) {
    __shared__ float sm[32];
    __shared__ float s_inv;
    float acc = 0.f;
    for (int i = threadIdx.x; i < n; i += 1024) { float x = v[i]; acc += x * x; }
    #pragma unroll
    for (int o = 16; o > 0; o >>= 1) acc += __shfl_down_sync(0xffffffffu, acc, o);
    if ((threadIdx.x & 31) == 0) sm[threadIdx.x >> 5] = acc;
    __syncthreads();
    if (threadIdx.x < 32) {
        float a = sm[threadIdx.x];
        #pragma unroll
        for (int o = 16; o > 0; o >>= 1) a += __shfl_down_sync(0xffffffffu, a, o);
        if (threadIdx.x == 0) s_inv = 1.0f / (sqrtf(a) + 1e-12f);
    }
    __syncthreads();
    float inv = s_inv;
    for (int i = threadIdx.x; i < n; i += 1024) v[i] *= inv;
}

__global__ void dot_kernel(const float* __restrict__ a, const float* __restrict__ b,
                           float* __restrict__ out, int n) {
    __shared__ float sm[32];
    float acc = 0.f;
    for (int i = threadIdx.x; i < n; i += 1024) acc += a[i] * b[i];
    #pragma unroll
    for (int o = 16; o > 0; o >>= 1) acc += __shfl_down_sync(0xffffffffu, acc, o);
    if ((threadIdx.x & 31) == 0) sm[threadIdx.x >> 5] = acc;
    __syncthreads();
    if (threadIdx.x < 32) {
        float a2 = sm[threadIdx.x];
        #pragma unroll
        for (int o = 16; o > 0; o >>= 1) a2 += __shfl_down_sync(0xffffffffu, a2, o);
        if (threadIdx.x == 0) out[0] = a2;
    }
}

// Wn = W / sigma, split into bf16 hi/lo pair
__global__ void scale_split(const float* __restrict__ W, const float* __restrict__ sig,
                            __nv_bfloat16* __restrict__ hi, __nv_bfloat16* __restrict__ lo,
                            size_t n) {
    float inv = 1.0f / sig[0];
    size_t stride = (size_t)gridDim.x * blockDim.x;
    for (size_t i = (size_t)blockIdx.x * blockDim.x + threadIdx.x; i < n; i += stride) {
        float w = W[i] * inv;
        __nv_bfloat16 h = __float2bfloat16(w);
        hi[i] = h;
        lo[i] = __float2bfloat16(w - __bfloat162float(h));
    }
}

// ---------------- layernorm: fp32 in, bf16 hi/lo out ----------------
__global__ void layernorm_split(const float* __restrict__ h,
                                const float* __restrict__ g, const float* __restrict__ b,
                                __nv_bfloat16* __restrict__ ohi, __nv_bfloat16* __restrict__ olo) {
    int row = blockIdx.x;
    const float* hr = h + (size_t)row * DH;
    float s = 0.f, ss = 0.f;
    float xl[4];
    #pragma unroll
    for (int t = 0; t < 4; t++) {
        float x = hr[threadIdx.x + t * 256];
        xl[t] = x; s += x; ss += x * x;
    }
    __shared__ float sm1[8], sm2[8];
    #pragma unroll
    for (int o = 16; o > 0; o >>= 1) {
        s  += __shfl_down_sync(0xffffffffu, s, o);
        ss += __shfl_down_sync(0xffffffffu, ss, o);
    }
    if ((threadIdx.x & 31) == 0) { sm1[threadIdx.x >> 5] = s; sm2[threadIdx.x >> 5] = ss; }
    __syncthreads();
    __shared__ float s_mu, s_inv;
    if (threadIdx.x < 8) {
        float a = sm1[threadIdx.x], c = sm2[threadIdx.x];
        #pragma unroll
        for (int o = 4; o > 0; o >>= 1) {
            a += __shfl_down_sync(0xffu, a, o);
            c += __shfl_down_sync(0xffu, c, o);
        }
        if (threadIdx.x == 0) {
            float mu  = a * (1.0f / DH);
            float var = c * (1.0f / DH) - mu * mu;
            s_mu = mu; s_inv = rsqrtf(var + LN_EPSF);
        }
    }
    __syncthreads();
    float mu = s_mu, inv = s_inv;
    #pragma unroll
    for (int t = 0; t < 4; t++) {
        int j = threadIdx.x + t * 256;
        float y = (xl[t] - mu) * inv * g[j] + b[j];
        __nv_bfloat16 hh = __float2bfloat16(y);
        size_t idx = (size_t)row * DH + j;
        ohi[idx] = hh;
        olo[idx] = __float2bfloat16(y - __bfloat162float(hh));
    }
}

// ---------------- HMMA bf16x3-split persistent GEMM ----------------
// C[M,N] = (Ahi+Alo)[M,K] @ ((Whi+Wlo)[N,K])^T, 3 first-order terms.
// CTA tile 256x128, 8 warps (4x2), warp tile 64x64 = 4x8 m16n8k16 frags.
// BK=32, 3-stage cp.async pipeline, persistent CTAs over flattened tile loop.
#define MSTAGES 3
#define ROWB    80
#define ATILEB  (256 * ROWB)             // 20480 B: 256x32 bf16 tile
#define WTILEB  (128 * ROWB)             // 10240 B: 128x32 bf16 tile
#define STAGEB  (2 * ATILEB + 2 * WTILEB)   // 61440 B
#define GSMEM   (MSTAGES * STAGEB)          // 184320 B

#define EPI_TANH 1
#define EPI_STEP 2

__device__ __forceinline__ void load_stage(
    uint32_t sbase, int buf, int k0,
    const __nv_bfloat16* __restrict__ Ahi, const __nv_bfloat16* __restrict__ Alo,
    const __nv_bfloat16* __restrict__ Whi, const __nv_bfloat16* __restrict__ Wlo,
    int bm, int bn, int K, int tid)
{
    uint32_t base = sbase + (uint32_t)buf * STAGEB;
    // A: 2 parts x 256 rows x 4 16B-chunks = 2048 lane-ops (8/thread)
    #pragma unroll
    for (int j = 0; j < 8; j++) {
        int c = tid + j * 256;                  // 0..2047
        int part = c >> 10;                     // 0=hi, 1=lo
        int rr = (c & 1023) >> 2, c16 = c & 3;
        const __nv_bfloat16* g = part ? Alo : Ahi;
        cp_async16(base + (uint32_t)(part * ATILEB + rr * ROWB + c16 * 16),
                   g + (size_t)(bm + rr) * K + k0 + c16 * 8);
    }
    // W: 2 parts x 128 rows x 4 chunks = 1024 lane-ops (4/thread)
    #pragma unroll
    for (int j = 0; j < 4; j++) {
        int c = tid + j * 256;                  // 0..1023
        int part = c >> 9;
        int rr = (c & 511) >> 2, c16 = c & 3;
        const __nv_bfloat16* g = part ? Wlo : Whi;
        cp_async16(base + (uint32_t)(2 * ATILEB + part * WTILEB + rr * ROWB + c16 * 16),
                   g + (size_t)(bn + rr) * K + k0 + c16 * 8);
    }
}

template <int EPI>
__global__ __launch_bounds__(256, 1) void gemm_mma_bf16x3(
    const __nv_bfloat16* __restrict__ Ahi, const __nv_bfloat16* __restrict__ Alo,
    const __nv_bfloat16* __restrict__ Whi, const __nv_bfloat16* __restrict__ Wlo,
    const float* __restrict__ bias, int N, int K, int ntiles, int nx,
    float* __restrict__ Cf,
    __nv_bfloat16* __restrict__ Chi, __nv_bfloat16* __restrict__ Clo,
    const float* __restrict__ hprev, const float* __restrict__ xemb, float gamma) {

    extern __shared__ __align__(128) char smem[];
    uint32_t sb = smem_u32(smem);
    int tid = threadIdx.x, wid = tid >> 5, lane = tid & 31;
    int m0 = (wid >> 1) * 64, n0 = (wid & 1) * 64;   // warp tile 64x64
    int r16 = lane & 15, kh = lane >> 4;
    int g8 = lane >> 3, l8 = lane & 7;
    int qr = lane >> 2, qc = (lane & 3) * 2;
    const int nch = K >> 5;

    for (int tile = blockIdx.x; tile < ntiles; tile += gridDim.x) {
        int bm = (tile / nx) * 256, bn = (tile % nx) * 128;

        float acc[4][8][4] = {};

        #pragma unroll
        for (int s = 0; s < MSTAGES - 1; s++) {
            load_stage(sb, s, s << 5, Ahi, Alo, Whi, Wlo, bm, bn, K, tid);
            cp_commit();
        }

        int bufi = 0;
        for (int i = 0; i < nch; i++) {
            cp_wait<MSTAGES - 2>();
            __syncthreads();

            uint32_t st = sb + (uint32_t)bufi * STAGEB;
            #pragma unroll
            for (int ks = 0; ks < 2; ks++) {
                uint32_t a_hi[4][4], a_lo[4][4], b_hi[4][4], b_lo[4][4];
                #pragma unroll
                for (int mt = 0; mt < 4; mt++) {
                    uint32_t ar = st + (uint32_t)((m0 + mt * 16 + r16) * ROWB + ks * 32 + kh * 16);
                    ldm_x4(ar, a_hi[mt]);
                    ldm_x4(ar + ATILEB, a_lo[mt]);
                }
                #pragma unroll
                for (int nh = 0; nh < 4; nh++) {
                    uint32_t br = st + 2 * ATILEB +
                        (uint32_t)((n0 + nh * 16 + (g8 >> 1) * 8 + l8) * ROWB + ks * 32 + (g8 & 1) * 16);
                    ldm_x4(br, b_hi[nh]);
                    ldm_x4(br + WTILEB, b_lo[nh]);
                }
                // term-outer ordering: 32 independent MMAs per term
                #pragma unroll
                for (int mt = 0; mt < 4; mt++)
                    #pragma unroll
                    for (int nt = 0; nt < 8; nt++)
                        mma16816(acc[mt][nt], a_hi[mt], &b_hi[nt >> 1][(nt & 1) * 2]);
                #pragma unroll
                for (int mt = 0; mt < 4; mt++)
                    #pragma unroll
                    for (int nt = 0; nt < 8; nt++)
                        mma16816(acc[mt][nt], a_hi[mt], &b_lo[nt >> 1][(nt & 1) * 2]);
                #pragma unroll
                for (int mt = 0; mt < 4; mt++)
                    #pragma unroll
                    for (int nt = 0; nt < 8; nt++)
                        mma16816(acc[mt][nt], a_lo[mt], &b_hi[nt >> 1][(nt & 1) * 2]);
            }

            int nxt = i + MSTAGES - 1;
            if (nxt < nch)
                load_stage(sb, (bufi + MSTAGES - 1 >= MSTAGES ? bufi - 1 : bufi + MSTAGES - 1),
                           nxt << 5, Ahi, Alo, Whi, Wlo, bm, bn, K, tid);
            cp_commit();
            bufi = (bufi + 1 == MSTAGES) ? 0 : bufi + 1;
        }

        // epilogue from accumulator registers
        #pragma unroll
        for (int mt = 0; mt < 4; mt++) {
            #pragma unroll
            for (int nt = 0; nt < 8; nt++) {
                int c0 = bn + n0 + nt * 8 + qc;
                float2 bz = *(const float2*)(bias + c0);
                #pragma unroll
                for (int h = 0; h < 2; h++) {
                    int r = bm + m0 + mt * 16 + qr + h * 8;
                    float v0 = acc[mt][nt][h * 2 + 0] + bz.x;
                    float v1 = acc[mt][nt][h * 2 + 1] + bz.y;
                    size_t idx = (size_t)r * N + c0;
                    if (EPI == EPI_TANH) {
                        float t0 = tanhf(v0), t1 = tanhf(v1);
                        __nv_bfloat16 h0 = __float2bfloat16(t0), h1 = __float2bfloat16(t1);
                        __nv_bfloat162 hp; hp.x = h0; hp.y = h1;
                        __nv_bfloat162 lp;
                        lp.x = __float2bfloat16(t0 - __bfloat162float(h0));
                        lp.y = __float2bfloat16(t1 - __bfloat162float(h1));
                        *(__nv_bfloat162*)(Chi + idx) = hp;
                        *(__nv_bfloat162*)(Clo + idx) = lp;
                    } else {
                        float2 hp = *(const float2*)(hprev + idx);
                        float2 xe = *(const float2*)(xemb + idx);
                        float2 o;
                        o.x = (1.0f - gamma) * hp.x + gamma * (v0 + xe.x);
                        o.y = (1.0f - gamma) * hp.y + gamma * (v1 + xe.y);
                        *(float2*)(Cf + idx) = o;
                    }
                }
            }
        }
        __syncthreads();   // protect smem buffers before next tile's prologue
    }
}

// ---------------- fp32 SIMT GEMM (embed + head only) ----------------
#define BM 128
#define BN 128
#define BK 8
#define TM 8
#define TN 8

__global__ __launch_bounds__(256, 2) void gemm_f32_bias(
    const float* __restrict__ A, const float* __restrict__ W,
    const float* __restrict__ bias, float* __restrict__ C,
    int M, int N, int K) {

    __shared__ __align__(16) float As[BK][BM];
    __shared__ __align__(16) float Ws[BK][BN];

    int tid = threadIdx.x;
    int bm = blockIdx.y * BM, bn = blockIdx.x * BN;
    const float* Ablk = A + (size_t)bm * K;
    const float* Wblk = W + (size_t)bn * K;

    int lrow = tid >> 1;
    int lcol = (tid & 1) * 4;
    int ty = tid >> 4, tx = tid & 15;

    float acc[TM][TN] = {};

    for (int k0 = 0; k0 < K; k0 += BK) {
        float4 a4 = *reinterpret_cast<const float4*>(Ablk + (size_t)lrow * K + k0 + lcol);
        float4 w4 = *reinterpret_cast<const float4*>(Wblk + (size_t)lrow * K + k0 + lcol);
        As[lcol + 0][lrow] = a4.x; As[lcol + 1][lrow] = a4.y;
        As[lcol + 2][lrow] = a4.z; As[lcol + 3][lrow] = a4.w;
        Ws[lcol + 0][lrow] = w4.x; Ws[lcol + 1][lrow] = w4.y;
        Ws[lcol + 2][lrow] = w4.z; Ws[lcol + 3][lrow] = w4.w;
        __syncthreads();
        #pragma unroll
        for (int k = 0; k < BK; k++) {
            float4 a0 = *reinterpret_cast<const float4*>(&As[k][ty * TM]);
            float4 a1 = *reinterpret_cast<const float4*>(&As[k][ty * TM + 4]);
            float4 w0 = *reinterpret_cast<const float4*>(&Ws[k][tx * TN]);
            float4 w1 = *reinterpret_cast<const float4*>(&Ws[k][tx * TN + 4]);
            float ra[TM] = {a0.x, a0.y, a0.z, a0.w, a1.x, a1.y, a1.z, a1.w};
            float rw[TN] = {w0.x, w0.y, w0.z, w0.w, w1.x, w1.y, w1.z, w1.w};
            #pragma unroll
            for (int i = 0; i < TM; i++)
                #pragma unroll
                for (int j = 0; j < TN; j++)
                    acc[i][j] += ra[i] * rw[j];
        }
        __syncthreads();
    }

    #pragma unroll
    for (int i = 0; i < TM; i++) {
        int m = bm + ty * TM + i;
        #pragma unroll
        for (int j = 0; j < TN; j++) {
            int n = bn + tx * TN + j;
            C[(size_t)m * N + n] = acc[i][j] + bias[n];
        }
    }
}

// ---------------- host-side helpers ----------------
static void spectral_sigma(const float* W, int R, int C,
                           float* u, float* v, float* t, float* sig) {
    float v0 = 1.0f / sqrtf((float)C);
    init_vec_kernel<<<(C + 255) / 256, 256>>>(v, C, v0);
    for (int it = 0; it < 15; it++) {
        matvec_rows<<<R, 256>>>(W, v, u, C);
        normalize_vec<<<1, 1024>>>(u, R);
        init_vec_kernel<<<(C + 255) / 256, 256>>>(v, C, 0.f);
        matvec_cols<<<dim3(C / 32, 8), 256>>>(W, u, v, R, C);
        normalize_vec<<<1, 1024>>>(v, C);
    }
    matvec_rows<<<R, 256>>>(W, v, t, C);
    dot_kernel<<<1, 1024>>>(u, t, sig, R);
}

extern "C" void kernel_launch(void* const* d_in, const int* in_sizes, int n_in,
                              void* d_out, int out_size) {
    const float* x       = (const float*)d_in[0];
    const float* embed_w = (const float*)d_in[1];
    const float* embed_b = (const float*)d_in[2];
    const float* W1      = (const float*)d_in[3];
    const float* b1      = (const float*)d_in[4];
    const float* W2      = (const float*)d_in[5];
    const float* b2      = (const float*)d_in[6];
    const float* ln_g    = (const float*)d_in[7];
    const float* ln_b    = (const float*)d_in[8];
    const float* head_w  = (const float*)d_in[9];
    const float* head_b  = (const float*)d_in[10];
    float* out = (float*)d_out;

    float *p_xemb, *p_hA, *p_hB, *p_u, *p_v, *p_t, *p_sig;
    __nv_bfloat16 *p_W1hi, *p_W1lo, *p_W2hi, *p_W2lo, *p_hnhi, *p_hnlo, *p_hidhi, *p_hidlo;
    cudaGetSymbolAddress((void**)&p_xemb, g_xemb);
    cudaGetSymbolAddress((void**)&p_hA, g_hA);
    cudaGetSymbolAddress((void**)&p_hB, g_hB);
    cudaGetSymbolAddress((void**)&p_u, g_u);
    cudaGetSymbolAddress((void**)&p_v, g_v);
    cudaGetSymbolAddress((void**)&p_t, g_t);
    cudaGetSymbolAddress((void**)&p_sig, g_sig);
    cudaGetSymbolAddress((void**)&p_W1hi, g_W1hi);
    cudaGetSymbolAddress((void**)&p_W1lo, g_W1lo);
    cudaGetSymbolAddress((void**)&p_W2hi, g_W2hi);
    cudaGetSymbolAddress((void**)&p_W2lo, g_W2lo);
    cudaGetSymbolAddress((void**)&p_hnhi, g_hnhi);
    cudaGetSymbolAddress((void**)&p_hnlo, g_hnlo);
    cudaGetSymbolAddress((void**)&p_hidhi, g_hidhi);
    cudaGetSymbolAddress((void**)&p_hidlo, g_hidlo);

    cudaFuncSetAttribute(gemm_mma_bf16x3<EPI_TANH>,
                         cudaFuncAttributeMaxDynamicSharedMemorySize, GSMEM);
    cudaFuncSetAttribute(gemm_mma_bf16x3<EPI_STEP>,
                         cudaFuncAttributeMaxDynamicSharedMemorySize, GSMEM);

    // spectral sigma + bf16 hi/lo split of W1n, W2n
    spectral_sigma(W1, DFF, DH, p_u, p_v, p_t, p_sig);
    scale_split<<<2048, 256>>>(W1, p_sig, p_W1hi, p_W1lo, (size_t)DFF * DH);
    spectral_sigma(W2, DH, DFF, p_u, p_v, p_t, p_sig);
    scale_split<<<2048, 256>>>(W2, p_sig, p_W2hi, p_W2lo, (size_t)DH * DFF);

    // x_emb = x @ embed_w^T + embed_b  (fp32 SIMT)
    gemm_f32_bias<<<dim3(DH / BN, B_ / BM), 256>>>(x, embed_w, embed_b, p_xemb, B_, DH, DIN);

    // h0 = x_emb
    cudaMemcpyAsync(p_hA, p_xemb, (size_t)B_ * DH * sizeof(float), cudaMemcpyDeviceToDevice);

    const int nt1 = (B_ / 256) * (DFF / 128);   // 512 tiles, nx=32
    const int nt2 = (B_ / 256) * (DH / 128);    // 128 tiles, nx=8

    float* hc = p_hA;
    float* hx = p_hB;
    for (int s = 0; s < STEPS; s++) {
        layernorm_split<<<B_, 256>>>(hc, ln_g, ln_b, p_hnhi, p_hnlo);
        gemm_mma_bf16x3<EPI_TANH><<<NSM, 256, GSMEM>>>(
            p_hnhi, p_hnlo, p_W1hi, p_W1lo, b1, DFF, DH, nt1, DFF / 128,
            nullptr, p_hidhi, p_hidlo, nullptr, nullptr, 0.f);
        gemm_mma_bf16x3<EPI_STEP><<<NSM, 256, GSMEM>>>(
            p_hidhi, p_hidlo, p_W2hi, p_W2lo, b2, DH, DFF, nt2, DH / 128,
            hx, nullptr, nullptr, hc, p_xemb, GAMMA_F);
        float* tmp = hc; hc = hx; hx = tmp;
    }

    // out = h @ head_w^T + head_b (fp32 SIMT)
    gemm_f32_bias<<<dim3(DOUT / BN, B_ / BM), 256>>>(hc, head_w, head_b, out, B_, DOUT, DH);
}

// round 7
// speedup vs baseline: 3.1559x; 1.1006x over previous
#include <cuda_runtime.h>
#include <cuda_bf16.h>
#include <math.h>
#include <cstddef>
#include <cstdint>

// ---------------- problem constants ----------------
#define B_    4096
#define DIN   512
#define DH    1024
#define DOUT  256
#define DFF   4096
#define STEPS 30
#define LN_EPSF 1e-5f
#define GAMMA_F 0.17677669529663687f   // 0.5*sqrt(64/512)
#define NSM   148

// ---------------- device scratch (no allocations allowed) ----------------
__device__ float g_xemb[(size_t)B_ * DH];
__device__ float g_hA[(size_t)B_ * DH];
__device__ float g_hB[(size_t)B_ * DH];
__device__ __nv_bfloat16 g_W1hi[(size_t)DFF * DH];
__device__ __nv_bfloat16 g_W1lo[(size_t)DFF * DH];
__device__ __nv_bfloat16 g_W2hi[(size_t)DH * DFF];
__device__ __nv_bfloat16 g_W2lo[(size_t)DH * DFF];
__device__ __nv_bfloat16 g_hnhi[(size_t)B_ * DH];
__device__ __nv_bfloat16 g_hnlo[(size_t)B_ * DH];
__device__ __nv_bfloat16 g_hidhi[(size_t)B_ * DFF];
__device__ __nv_bfloat16 g_hidlo[(size_t)B_ * DFF];
__device__ float g_u[4096];
__device__ float g_v[4096];
__device__ float g_t[4096];
__device__ float g_sig[2];

// ---------------- low-level helpers (plain sm_80+ features only) ----------------
__device__ __forceinline__ uint32_t smem_u32(const void* p) {
    uint32_t a;
    asm("{ .reg .u64 t; cvta.to.shared.u64 t, %1; cvt.u32.u64 %0, t; }" : "=r"(a) : "l"(p));
    return a;
}
__device__ __forceinline__ void cp_async16(uint32_t dst, const void* src) {
    asm volatile("cp.async.cg.shared.global [%0], [%1], 16;" :: "r"(dst), "l"(src) : "memory");
}
__device__ __forceinline__ void cp_commit() {
    asm volatile("cp.async.commit_group;" ::: "memory");
}
template<int N> __device__ __forceinline__ void cp_wait() {
    asm volatile("cp.async.wait_group %0;" :: "n"(N) : "memory");
}
__device__ __forceinline__ void ldm_x4(uint32_t addr, uint32_t* r) {
    asm volatile("ldmatrix.sync.aligned.m8n8.x4.shared.b16 {%0,%1,%2,%3}, [%4];"
        : "=r"(r[0]), "=r"(r[1]), "=r"(r[2]), "=r"(r[3]) : "r"(addr));
}
__device__ __forceinline__ void mma16816(float* d, const uint32_t* a, const uint32_t* b) {
    asm volatile("mma.sync.aligned.m16n8k16.row.col.f32.bf16.bf16.f32 "
        "{%0,%1,%2,%3}, {%4,%5,%6,%7}, {%8,%9}, {%0,%1,%2,%3};"
        : "+f"(d[0]), "+f"(d[1]), "+f"(d[2]), "+f"(d[3])
        : "r"(a[0]), "r"(a[1]), "r"(a[2]), "r"(a[3]), "r"(b[0]), "r"(b[1]));
}
// swizzled offset inside a tile: row r (64B rows), 16B-chunk c (0..3)
__device__ __forceinline__ uint32_t sw_off(int r, int c) {
    return ((uint32_t)r << 6) + (uint32_t)((c ^ ((r >> 1) & 3)) << 4);
}

// ---------------- small kernels: spectral norm ----------------
__global__ void init_vec_kernel(float* v, int n, float val) {
    int i = blockIdx.x * blockDim.x + threadIdx.x;
    if (i < n) v[i] = val;
}

__global__ void matvec_rows(const float* __restrict__ W, const float* __restrict__ v,
                            float* __restrict__ y, int C) {
    int row = blockIdx.x;
    const float* Wr = W + (size_t)row * C;
    float acc = 0.f;
    for (int j = threadIdx.x; j < C; j += 256) acc += Wr[j] * v[j];
    __shared__ float sm[8];
    #pragma unroll
    for (int o = 16; o > 0; o >>= 1) acc += __shfl_down_sync(0xffffffffu, acc, o);
    if ((threadIdx.x & 31) == 0) sm[threadIdx.x >> 5] = acc;
    __syncthreads();
    if (threadIdx.x < 8) {
        float a = sm[threadIdx.x];
        #pragma unroll
        for (int o = 4; o > 0; o >>= 1) a += __shfl_down_sync(0xffu, a, o);
        if (threadIdx.x == 0) y[row] = a;
    }
}

// z[col] += partial dot(W[:,col], u); grid (C/32, 8); z must be zeroed first
__global__ void matvec_cols(const float* __restrict__ W, const float* __restrict__ u,
                            float* __restrict__ z, int R, int C) {
    int lane = threadIdx.x & 31;
    int rp   = threadIdx.x >> 5;
    int col  = blockIdx.x * 32 + lane;
    int rchunk = R >> 3;
    int r0 = blockIdx.y * rchunk;
    int r1 = r0 + rchunk;
    float acc = 0.f;
    for (int i = r0 + rp; i < r1; i += 8) acc += W[(size_t)i * C + col] * u[i];
    __shared__ float sm[8][33];
    sm[rp][lane] = acc;
    __syncthreads();
    if (rp == 0) {
        float a = 0.f;
        #pragma unroll
        for (int r = 0; r < 8; r++) a += sm[r][lane];
        atomicAdd(&z[col], a);
    }
}

__global__ void normalize_vec(float* v, int n) {
    __shared__ float sm[32];
    __shared__ float s_inv;
    float acc = 0.f;
    for (int i = threadIdx.x; i < n; i += 1024) { float x = v[i]; acc += x * x; }
    #pragma unroll
    for (int o = 16; o > 0; o >>= 1) acc += __shfl_down_sync(0xffffffffu, acc, o);
    if ((threadIdx.x & 31) == 0) sm[threadIdx.x >> 5] = acc;
    __syncthreads();
    if (threadIdx.x < 32) {
        float a = sm[threadIdx.x];
        #pragma unroll
        for (int o = 16; o > 0; o >>= 1) a += __shfl_down_sync(0xffffffffu, a, o);
        if (threadIdx.x == 0) s_inv = 1.0f / (sqrtf(a) + 1e-12f);
    }
    __syncthreads();
    float inv = s_inv;
    for (int i = threadIdx.x; i < n; i += 1024) v[i] *= inv;
}

__global__ void dot_kernel(const float* __restrict__ a, const float* __restrict__ b,
                           float* __restrict__ out, int n) {
    __shared__ float sm[32];
    float acc = 0.f;
    for (int i = threadIdx.x; i < n; i += 1024) acc += a[i] * b[i];
    #pragma unroll
    for (int o = 16; o > 0; o >>= 1) acc += __shfl_down_sync(0xffffffffu, acc, o);
    if ((threadIdx.x & 31) == 0) sm[threadIdx.x >> 5] = acc;
    __syncthreads();
    if (threadIdx.x < 32) {
        float a2 = sm[threadIdx.x];
        #pragma unroll
        for (int o = 16; o > 0; o >>= 1) a2 += __shfl_down_sync(0xffffffffu, a2, o);
        if (threadIdx.x == 0) out[0] = a2;
    }
}

// Wn = W / sigma, split into bf16 hi/lo pair
__global__ void scale_split(const float* __restrict__ W, const float* __restrict__ sig,
                            __nv_bfloat16* __restrict__ hi, __nv_bfloat16* __restrict__ lo,
                            size_t n) {
    float inv = 1.0f / sig[0];
    size_t stride = (size_t)gridDim.x * blockDim.x;
    for (size_t i = (size_t)blockIdx.x * blockDim.x + threadIdx.x; i < n; i += stride) {
        float w = W[i] * inv;
        __nv_bfloat16 h = __float2bfloat16(w);
        hi[i] = h;
        lo[i] = __float2bfloat16(w - __bfloat162float(h));
    }
}

// ---------------- layernorm: fp32 in, bf16 hi/lo out ----------------
__global__ void layernorm_split(const float* __restrict__ h,
                                const float* __restrict__ g, const float* __restrict__ b,
                                __nv_bfloat16* __restrict__ ohi, __nv_bfloat16* __restrict__ olo) {
    int row = blockIdx.x;
    const float* hr = h + (size_t)row * DH;
    float s = 0.f, ss = 0.f;
    float xl[4];
    #pragma unroll
    for (int t = 0; t < 4; t++) {
        float x = hr[threadIdx.x + t * 256];
        xl[t] = x; s += x; ss += x * x;
    }
    __shared__ float sm1[8], sm2[8];
    #pragma unroll
    for (int o = 16; o > 0; o >>= 1) {
        s  += __shfl_down_sync(0xffffffffu, s, o);
        ss += __shfl_down_sync(0xffffffffu, ss, o);
    }
    if ((threadIdx.x & 31) == 0) { sm1[threadIdx.x >> 5] = s; sm2[threadIdx.x >> 5] = ss; }
    __syncthreads();
    __shared__ float s_mu, s_inv;
    if (threadIdx.x < 8) {
        float a = sm1[threadIdx.x], c = sm2[threadIdx.x];
        #pragma unroll
        for (int o = 4; o > 0; o >>= 1) {
            a += __shfl_down_sync(0xffu, a, o);
            c += __shfl_down_sync(0xffu, c, o);
        }
        if (threadIdx.x == 0) {
            float mu  = a * (1.0f / DH);
            float var = c * (1.0f / DH) - mu * mu;
            s_mu = mu; s_inv = rsqrtf(var + LN_EPSF);
        }
    }
    __syncthreads();
    float mu = s_mu, inv = s_inv;
    #pragma unroll
    for (int t = 0; t < 4; t++) {
        int j = threadIdx.x + t * 256;
        float y = (xl[t] - mu) * inv * g[j] + b[j];
        __nv_bfloat16 hh = __float2bfloat16(y);
        size_t idx = (size_t)row * DH + j;
        ohi[idx] = hh;
        olo[idx] = __float2bfloat16(y - __bfloat162float(hh));
    }
}

// ---------------- HMMA bf16x3-split persistent GEMM ----------------
// C[M,N] = (Ahi+Alo)[M,K] @ ((Whi+Wlo)[N,K])^T, 3 first-order terms.
// CTA tile 256x128, 8 warps (4x2), warp tile 64x64 = 4x8 m16n8k16 frags.
// BK=32, 4-stage cp.async pipeline, 64B XOR-swizzled rows (conflict-free
// for both ldmatrix reads and cp.async 16B stores), persistent CTAs.
#define MSTAGES 4
#define ATILEB  (256 * 64)               // 16384 B: 256x32 bf16 tile
#define WTILEB  (128 * 64)               //  8192 B: 128x32 bf16 tile
#define STAGEB  (2 * ATILEB + 2 * WTILEB)   // 49152 B
#define GSMEM   (MSTAGES * STAGEB)          // 196608 B

#define EPI_TANH 1
#define EPI_STEP 2

__device__ __forceinline__ void load_stage(
    uint32_t sbase, int buf, int k0,
    const __nv_bfloat16* __restrict__ Ahi, const __nv_bfloat16* __restrict__ Alo,
    const __nv_bfloat16* __restrict__ Whi, const __nv_bfloat16* __restrict__ Wlo,
    int bm, int bn, int K, int tid)
{
    uint32_t base = sbase + (uint32_t)buf * STAGEB;
    // A: 2 parts x 256 rows x 4 16B-chunks = 2048 lane-ops (8/thread)
    #pragma unroll
    for (int j = 0; j < 8; j++) {
        int c = tid + j * 256;                  // 0..2047
        int part = c >> 10;                     // 0=hi, 1=lo
        int rr = (c & 1023) >> 2, c16 = c & 3;
        const __nv_bfloat16* g = part ? Alo : Ahi;
        cp_async16(base + (uint32_t)part * ATILEB + sw_off(rr, c16),
                   g + (size_t)(bm + rr) * K + k0 + c16 * 8);
    }
    // W: 2 parts x 128 rows x 4 chunks = 1024 lane-ops (4/thread)
    #pragma unroll
    for (int j = 0; j < 4; j++) {
        int c = tid + j * 256;                  // 0..1023
        int part = c >> 9;
        int rr = (c & 511) >> 2, c16 = c & 3;
        const __nv_bfloat16* g = part ? Wlo : Whi;
        cp_async16(base + 2u * ATILEB + (uint32_t)part * WTILEB + sw_off(rr, c16),
                   g + (size_t)(bn + rr) * K + k0 + c16 * 8);
    }
}

template <int EPI>
__global__ __launch_bounds__(256, 1) void gemm_mma_bf16x3(
    const __nv_bfloat16* __restrict__ Ahi, const __nv_bfloat16* __restrict__ Alo,
    const __nv_bfloat16* __restrict__ Whi, const __nv_bfloat16* __restrict__ Wlo,
    const float* __restrict__ bias, int N, int K, int ntiles, int nx,
    float* __restrict__ Cf,
    __nv_bfloat16* __restrict__ Chi, __nv_bfloat16* __restrict__ Clo,
    const float* __restrict__ hprev, const float* __restrict__ xemb, float gamma) {

    extern __shared__ __align__(128) char smem[];
    uint32_t sb = smem_u32(smem);
    int tid = threadIdx.x, wid = tid >> 5, lane = tid & 31;
    int m0 = (wid >> 1) * 64, n0 = (wid & 1) * 64;   // warp tile 64x64
    int r16 = lane & 15, kh = lane >> 4;
    int g8 = lane >> 3, l8 = lane & 7;
    int qr = lane >> 2, qc = (lane & 3) * 2;
    const int nch = K >> 5;

    for (int tile = blockIdx.x; tile < ntiles; tile += gridDim.x) {
        int bm = (tile / nx) * 256, bn = (tile % nx) * 128;

        float acc[4][8][4] = {};

        #pragma unroll
        for (int s = 0; s < MSTAGES - 1; s++) {
            load_stage(sb, s, s << 5, Ahi, Alo, Whi, Wlo, bm, bn, K, tid);
            cp_commit();
        }

        for (int i = 0; i < nch; i++) {
            cp_wait<MSTAGES - 2>();
            __syncthreads();

            uint32_t st = sb + (uint32_t)(i & (MSTAGES - 1)) * STAGEB;
            #pragma unroll
            for (int ks = 0; ks < 2; ks++) {
                uint32_t a_hi[4][4], a_lo[4][4], b_hi[4][4], b_lo[4][4];
                #pragma unroll
                for (int mt = 0; mt < 4; mt++) {
                    uint32_t ar = st + sw_off(m0 + mt * 16 + r16, ks * 2 + kh);
                    ldm_x4(ar, a_hi[mt]);
                    ldm_x4(ar + ATILEB, a_lo[mt]);
                }
                #pragma unroll
                for (int nh = 0; nh < 4; nh++) {
                    uint32_t br = st + 2 * ATILEB +
                        sw_off(n0 + nh * 16 + (g8 >> 1) * 8 + l8, ks * 2 + (g8 & 1));
                    ldm_x4(br, b_hi[nh]);
                    ldm_x4(br + WTILEB, b_lo[nh]);
                }
                // term-outer ordering: 32 independent MMAs per term
                #pragma unroll
                for (int mt = 0; mt < 4; mt++)
                    #pragma unroll
                    for (int nt = 0; nt < 8; nt++)
                        mma16816(acc[mt][nt], a_hi[mt], &b_hi[nt >> 1][(nt & 1) * 2]);
                #pragma unroll
                for (int mt = 0; mt < 4; mt++)
                    #pragma unroll
                    for (int nt = 0; nt < 8; nt++)
                        mma16816(acc[mt][nt], a_hi[mt], &b_lo[nt >> 1][(nt & 1) * 2]);
                #pragma unroll
                for (int mt = 0; mt < 4; mt++)
                    #pragma unroll
                    for (int nt = 0; nt < 8; nt++)
                        mma16816(acc[mt][nt], a_lo[mt], &b_hi[nt >> 1][(nt & 1) * 2]);
            }

            int nxt = i + MSTAGES - 1;
            if (nxt < nch)
                load_stage(sb, nxt & (MSTAGES - 1), nxt << 5, Ahi, Alo, Whi, Wlo, bm, bn, K, tid);
            cp_commit();
        }

        // epilogue from accumulator registers
        #pragma unroll
        for (int mt = 0; mt < 4; mt++) {
            #pragma unroll
            for (int nt = 0; nt < 8; nt++) {
                int c0 = bn + n0 + nt * 8 + qc;
                float2 bz = *(const float2*)(bias + c0);
                #pragma unroll
                for (int h = 0; h < 2; h++) {
                    int r = bm + m0 + mt * 16 + qr + h * 8;
                    float v0 = acc[mt][nt][h * 2 + 0] + bz.x;
                    float v1 = acc[mt][nt][h * 2 + 1] + bz.y;
                    size_t idx = (size_t)r * N + c0;
                    if (EPI == EPI_TANH) {
                        float t0 = tanhf(v0), t1 = tanhf(v1);
                        __nv_bfloat16 h0 = __float2bfloat16(t0), h1 = __float2bfloat16(t1);
                        __nv_bfloat162 hp; hp.x = h0; hp.y = h1;
                        __nv_bfloat162 lp;
                        lp.x = __float2bfloat16(t0 - __bfloat162float(h0));
                        lp.y = __float2bfloat16(t1 - __bfloat162float(h1));
                        *(__nv_bfloat162*)(Chi + idx) = hp;
                        *(__nv_bfloat162*)(Clo + idx) = lp;
                    } else {
                        float2 hp = *(const float2*)(hprev + idx);
                        float2 xe = *(const float2*)(xemb + idx);
                        float2 o;
                        o.x = (1.0f - gamma) * hp.x + gamma * (v0 + xe.x);
                        o.y = (1.0f - gamma) * hp.y + gamma * (v1 + xe.y);
                        *(float2*)(Cf + idx) = o;
                    }
                }
            }
        }
        __syncthreads();   // protect smem buffers before next tile's prologue
    }
}

// ---------------- fp32 SIMT GEMM (embed + head only) ----------------
#define BM 128
#define BN 128
#define BK 8
#define TM 8
#define TN 8

__global__ __launch_bounds__(256, 2) void gemm_f32_bias(
    const float* __restrict__ A, const float* __restrict__ W,
    const float* __restrict__ bias, float* __restrict__ C,
    int M, int N, int K) {

    __shared__ __align__(16) float As[BK][BM];
    __shared__ __align__(16) float Ws[BK][BN];

    int tid = threadIdx.x;
    int bm = blockIdx.y * BM, bn = blockIdx.x * BN;
    const float* Ablk = A + (size_t)bm * K;
    const float* Wblk = W + (size_t)bn * K;

    int lrow = tid >> 1;
    int lcol = (tid & 1) * 4;
    int ty = tid >> 4, tx = tid & 15;

    float acc[TM][TN] = {};

    for (int k0 = 0; k0 < K; k0 += BK) {
        float4 a4 = *reinterpret_cast<const float4*>(Ablk + (size_t)lrow * K + k0 + lcol);
        float4 w4 = *reinterpret_cast<const float4*>(Wblk + (size_t)lrow * K + k0 + lcol);
        As[lcol + 0][lrow] = a4.x; As[lcol + 1][lrow] = a4.y;
        As[lcol + 2][lrow] = a4.z; As[lcol + 3][lrow] = a4.w;
        Ws[lcol + 0][lrow] = w4.x; Ws[lcol + 1][lrow] = w4.y;
        Ws[lcol + 2][lrow] = w4.z; Ws[lcol + 3][lrow] = w4.w;
        __syncthreads();
        #pragma unroll
        for (int k = 0; k < BK; k++) {
            float4 a0 = *reinterpret_cast<const float4*>(&As[k][ty * TM]);
            float4 a1 = *reinterpret_cast<const float4*>(&As[k][ty * TM + 4]);
            float4 w0 = *reinterpret_cast<const float4*>(&Ws[k][tx * TN]);
            float4 w1 = *reinterpret_cast<const float4*>(&Ws[k][tx * TN + 4]);
            float ra[TM] = {a0.x, a0.y, a0.z, a0.w, a1.x, a1.y, a1.z, a1.w};
            float rw[TN] = {w0.x, w0.y, w0.z, w0.w, w1.x, w1.y, w1.z, w1.w};
            #pragma unroll
            for (int i = 0; i < TM; i++)
                #pragma unroll
                for (int j = 0; j < TN; j++)
                    acc[i][j] += ra[i] * rw[j];
        }
        __syncthreads();
    }

    #pragma unroll
    for (int i = 0; i < TM; i++) {
        int m = bm + ty * TM + i;
        #pragma unroll
        for (int j = 0; j < TN; j++) {
            int n = bn + tx * TN + j;
            C[(size_t)m * N + n] = acc[i][j] + bias[n];
        }
    }
}

// ---------------- host-side helpers ----------------
static void spectral_sigma(const float* W, int R, int C,
                           float* u, float* v, float* t, float* sig) {
    float v0 = 1.0f / sqrtf((float)C);
    init_vec_kernel<<<(C + 255) / 256, 256>>>(v, C, v0);
    for (int it = 0; it < 15; it++) {
        matvec_rows<<<R, 256>>>(W, v, u, C);
        normalize_vec<<<1, 1024>>>(u, R);
        init_vec_kernel<<<(C + 255) / 256, 256>>>(v, C, 0.f);
        matvec_cols<<<dim3(C / 32, 8), 256>>>(W, u, v, R, C);
        normalize_vec<<<1, 1024>>>(v, C);
    }
    matvec_rows<<<R, 256>>>(W, v, t, C);
    dot_kernel<<<1, 1024>>>(u, t, sig, R);
}

extern "C" void kernel_launch(void* const* d_in, const int* in_sizes, int n_in,
                              void* d_out, int out_size) {
    const float* x       = (const float*)d_in[0];
    const float* embed_w = (const float*)d_in[1];
    const float* embed_b = (const float*)d_in[2];
    const float* W1      = (const float*)d_in[3];
    const float* b1      = (const float*)d_in[4];
    const float* W2      = (const float*)d_in[5];
    const float* b2      = (const float*)d_in[6];
    const float* ln_g    = (const float*)d_in[7];
    const float* ln_b    = (const float*)d_in[8];
    const float* head_w  = (const float*)d_in[9];
    const float* head_b  = (const float*)d_in[10];
    float* out = (float*)d_out;

    float *p_xemb, *p_hA, *p_hB, *p_u, *p_v, *p_t, *p_sig;
    __nv_bfloat16 *p_W1hi, *p_W1lo, *p_W2hi, *p_W2lo, *p_hnhi, *p_hnlo, *p_hidhi, *p_hidlo;
    cudaGetSymbolAddress((void**)&p_xemb, g_xemb);
    cudaGetSymbolAddress((void**)&p_hA, g_hA);
    cudaGetSymbolAddress((void**)&p_hB, g_hB);
    cudaGetSymbolAddress((void**)&p_u, g_u);
    cudaGetSymbolAddress((void**)&p_v, g_v);
    cudaGetSymbolAddress((void**)&p_t, g_t);
    cudaGetSymbolAddress((void**)&p_sig, g_sig);
    cudaGetSymbolAddress((void**)&p_W1hi, g_W1hi);
    cudaGetSymbolAddress((void**)&p_W1lo, g_W1lo);
    cudaGetSymbolAddress((void**)&p_W2hi, g_W2hi);
    cudaGetSymbolAddress((void**)&p_W2lo, g_W2lo);
    cudaGetSymbolAddress((void**)&p_hnhi, g_hnhi);
    cudaGetSymbolAddress((void**)&p_hnlo, g_hnlo);
    cudaGetSymbolAddress((void**)&p_hidhi, g_hidhi);
    cudaGetSymbolAddress((void**)&p_hidlo, g_hidlo);

    cudaFuncSetAttribute(gemm_mma_bf16x3<EPI_TANH>,
                         cudaFuncAttributeMaxDynamicSharedMemorySize, GSMEM);
    cudaFuncSetAttribute(gemm_mma_bf16x3<EPI_STEP>,
                         cudaFuncAttributeMaxDynamicSharedMemorySize, GSMEM);

    // spectral sigma + bf16 hi/lo split of W1n, W2n
    spectral_sigma(W1, DFF, DH, p_u, p_v, p_t, p_sig);
    scale_split<<<2048, 256>>>(W1, p_sig, p_W1hi, p_W1lo, (size_t)DFF * DH);
    spectral_sigma(W2, DH, DFF, p_u, p_v, p_t, p_sig);
    scale_split<<<2048, 256>>>(W2, p_sig, p_W2hi, p_W2lo, (size_t)DH * DFF);

    // x_emb = x @ embed_w^T + embed_b  (fp32 SIMT)
    gemm_f32_bias<<<dim3(DH / BN, B_ / BM), 256>>>(x, embed_w, embed_b, p_xemb, B_, DH, DIN);

    // h0 = x_emb
    cudaMemcpyAsync(p_hA, p_xemb, (size_t)B_ * DH * sizeof(float), cudaMemcpyDeviceToDevice);

    const int nt1 = (B_ / 256) * (DFF / 128);   // 512 tiles, nx=32
    const int nt2 = (B_ / 256) * (DH / 128);    // 128 tiles, nx=8

    float* hc = p_hA;
    float* hx = p_hB;
    for (int s = 0; s < STEPS; s++) {
        layernorm_split<<<B_, 256>>>(hc, ln_g, ln_b, p_hnhi, p_hnlo);
        gemm_mma_bf16x3<EPI_TANH><<<NSM, 256, GSMEM>>>(
            p_hnhi, p_hnlo, p_W1hi, p_W1lo, b1, DFF, DH, nt1, DFF / 128,
            nullptr, p_hidhi, p_hidlo, nullptr, nullptr, 0.f);
        gemm_mma_bf16x3<EPI_STEP><<<NSM, 256, GSMEM>>>(
            p_hidhi, p_hidlo, p_W2hi, p_W2lo, b2, DH, DFF, nt2, DH / 128,
            hx, nullptr, nullptr, hc, p_xemb, GAMMA_F);
        float* tmp = hc; hc = hx; hx = tmp;
    }

    // out = h @ head_w^T + head_b (fp32 SIMT)
    gemm_f32_bias<<<dim3(DOUT / BN, B_ / BM), 256>>>(hc, head_w, head_b, out, B_, DOUT, DH);
}